// round 1
// baseline (speedup 1.0000x reference)
#include <cuda_runtime.h>
#include <cuda_bf16.h>
#include <math.h>

#define NN 160000
#define GG 800
#define NPG 200
#define EE 1280000
#define IN_F 31
#define HID 64
#define LD 64

#define SCAN_BS 512
#define SCAN_NB ((NN + SCAN_BS - 1) / SCAN_BS)   // 313

// ---------------- static device scratch (no allocation allowed) ----------------
__device__ int   g_deg[NN];
__device__ float g_norm[NN];
__device__ int   g_incl[NN];
__device__ int   g_bsums[1024];
__device__ int   g_rowptr[NN + 1];
__device__ int   g_cursor[NN];
__device__ int   g_col[EE];

__device__ float g_M0[NN * LD];
__device__ float g_M1[NN * LD];
__device__ float g_T1[NN * LD];
__device__ float g_T2[NN * LD];

// ---------------- degree / norm ----------------
__global__ void k_zero_deg() {
    int i = blockIdx.x * blockDim.x + threadIdx.x;
    if (i < NN) g_deg[i] = 0;
}

__global__ void k_deg(const int* __restrict__ dst) {
    int i = blockIdx.x * blockDim.x + threadIdx.x;
    if (i < EE) atomicAdd(&g_deg[dst[i]], 1);
}

__global__ void k_norm() {
    int i = blockIdx.x * blockDim.x + threadIdx.x;
    if (i < NN) g_norm[i] = rsqrtf(fmaxf((float)g_deg[i], 1.0f));
}

// ---------------- scan (3-kernel exclusive scan of deg -> rowptr) ----------------
__global__ void k_scan1() {
    __shared__ int sh[SCAN_BS];
    int i = blockIdx.x * SCAN_BS + threadIdx.x;
    int v = (i < NN) ? g_deg[i] : 0;
    sh[threadIdx.x] = v;
    __syncthreads();
    for (int off = 1; off < SCAN_BS; off <<= 1) {
        int t = (threadIdx.x >= off) ? sh[threadIdx.x - off] : 0;
        __syncthreads();
        sh[threadIdx.x] += t;
        __syncthreads();
    }
    if (i < NN) g_incl[i] = sh[threadIdx.x];
    if (threadIdx.x == SCAN_BS - 1) g_bsums[blockIdx.x] = sh[threadIdx.x];
}

__global__ void k_scan2() {   // single block, 1024 threads: exclusive scan of block sums
    __shared__ int sh[1024];
    int t = threadIdx.x;
    int orig = (t < SCAN_NB) ? g_bsums[t] : 0;
    sh[t] = orig;
    __syncthreads();
    for (int off = 1; off < 1024; off <<= 1) {
        int v = (t >= off) ? sh[t - off] : 0;
        __syncthreads();
        sh[t] += v;
        __syncthreads();
    }
    if (t < SCAN_NB) g_bsums[t] = sh[t] - orig;   // exclusive
}

__global__ void k_scan3() {
    int i = blockIdx.x * blockDim.x + threadIdx.x;
    if (i < NN) {
        int ex = g_incl[i] - g_deg[i] + g_bsums[i / SCAN_BS];
        g_rowptr[i] = ex;
        g_cursor[i] = ex;
    }
    if (i == 0) g_rowptr[NN] = EE;
}

__global__ void k_fill(const int* __restrict__ src, const int* __restrict__ dst) {
    int i = blockIdx.x * blockDim.x + threadIdx.x;
    if (i < EE) {
        int p = atomicAdd(&g_cursor[dst[i]], 1);
        g_col[p] = src[i];
    }
}

// ---------------- pad x [N,31] -> M0 [N,64] (zero-padded) ----------------
__global__ void k_pad(const float* __restrict__ x) {
    int i = blockIdx.x * blockDim.x + threadIdx.x;
    if (i < NN * LD) {
        int node = i >> 6, c = i & 63;
        g_M0[i] = (c < IN_F) ? x[node * IN_F + c] : 0.0f;
    }
}

// ---------------- SpMM hop: out[v] = norm[v] * sum_{u in in(v)} norm[u]*Hin[u] ----------------
template <bool TWO>
__global__ void k_spmm(const float* __restrict__ Hin, float* __restrict__ Hout) {
    int node = blockIdx.x * blockDim.y + threadIdx.y;
    if (node >= NN) return;
    int lane = threadIdx.x;
    int s = g_rowptr[node], e = g_rowptr[node + 1];
    float a0 = 0.f, a1 = 0.f;
    for (int j = s; j < e; j++) {
        int u = g_col[j];
        float nu = __ldg(&g_norm[u]);
        a0 += nu * __ldg(&Hin[u * LD + lane]);
        if (TWO) a1 += nu * __ldg(&Hin[u * LD + lane + 32]);
    }
    float nv = g_norm[node];
    Hout[node * LD + lane] = nv * a0;
    if (TWO) Hout[node * LD + lane + 32] = nv * a1;
    else     Hout[node * LD + lane + 32] = 0.0f;
}

// ---------------- fused concat-GEMM + bias + ReLU ----------------
// Out[n, j] = relu(b[j] + sum_k H0[n,k]W[k,j] + H1[n,k]W[F+k,j] + H2[n,k]W[2F+k,j])
// block: 256 threads, 32 rows per block; thread = (col in 0..31 -> cols col,col+32; 4 rows)
template <int F>
__global__ void k_gemm_relu(const float* __restrict__ H0, const float* __restrict__ H1,
                            const float* __restrict__ H2, const float* __restrict__ W,
                            const float* __restrict__ bias, float* __restrict__ Out) {
    constexpr int KK = 3 * F;
    extern __shared__ float sm[];
    float* Wsh = sm;              // [KK][64]
    float* Hsh = sm + KK * 64;    // [32][KK]
    int t = threadIdx.x;
    int row0 = blockIdx.x * 32;

    for (int i = t; i < KK * 64; i += 256) Wsh[i] = W[i];

    const float* bufs[3] = {H0, H1, H2};
#pragma unroll
    for (int hop = 0; hop < 3; hop++) {
        const float* Hx = bufs[hop];
        for (int idx = t; idx < 32 * F; idx += 256) {
            int r = idx / F, c = idx - r * F;
            Hsh[r * KK + hop * F + c] = Hx[(row0 + r) * LD + c];
        }
    }
    __syncthreads();

    int col = t & 31;
    int rbase = (t >> 5) * 4;
    float acc00 = 0.f, acc01 = 0.f, acc10 = 0.f, acc11 = 0.f;
    float acc20 = 0.f, acc21 = 0.f, acc30 = 0.f, acc31 = 0.f;
    const float* hrow = &Hsh[rbase * KK];

#pragma unroll 4
    for (int k = 0; k < KK; k++) {
        float w0 = Wsh[k * 64 + col];
        float w1 = Wsh[k * 64 + col + 32];
        float h0 = hrow[k];
        float h1 = hrow[KK + k];
        float h2 = hrow[2 * KK + k];
        float h3 = hrow[3 * KK + k];
        acc00 += h0 * w0; acc01 += h0 * w1;
        acc10 += h1 * w0; acc11 += h1 * w1;
        acc20 += h2 * w0; acc21 += h2 * w1;
        acc30 += h3 * w0; acc31 += h3 * w1;
    }
    float b0 = bias[col], b1 = bias[col + 32];
    int row = row0 + rbase;
    Out[(row + 0) * LD + col]      = fmaxf(acc00 + b0, 0.f);
    Out[(row + 0) * LD + col + 32] = fmaxf(acc01 + b1, 0.f);
    Out[(row + 1) * LD + col]      = fmaxf(acc10 + b0, 0.f);
    Out[(row + 1) * LD + col + 32] = fmaxf(acc11 + b1, 0.f);
    Out[(row + 2) * LD + col]      = fmaxf(acc20 + b0, 0.f);
    Out[(row + 2) * LD + col + 32] = fmaxf(acc21 + b1, 0.f);
    Out[(row + 3) * LD + col]      = fmaxf(acc30 + b0, 0.f);
    Out[(row + 3) * LD + col + 32] = fmaxf(acc31 + b1, 0.f);
}

// ---------------- per-graph attention pooling (nodes contiguous per graph) ----------------
__global__ void k_pool(const float* __restrict__ H, const float* __restrict__ Wg,
                       const float* __restrict__ bg, float* __restrict__ out) {
    int g = blockIdx.x;
    __shared__ float sWg[64];
    __shared__ float sgate[NPG];
    __shared__ float red[256];
    int t = threadIdx.x;
    if (t < 64) sWg[t] = Wg[t];
    __syncthreads();

    int lane = t & 31, w = t >> 5;
    float bgv = bg[0];
    for (int n = w; n < NPG; n += 8) {
        const float* hp = H + (size_t)(g * NPG + n) * LD;
        float v = hp[lane] * sWg[lane] + hp[lane + 32] * sWg[lane + 32];
#pragma unroll
        for (int o = 16; o; o >>= 1) v += __shfl_xor_sync(0xffffffffu, v, o);
        if (lane == 0) sgate[n] = v + bgv;
    }
    __syncthreads();

    float m = -INFINITY;
    for (int n = t; n < NPG; n += 256) m = fmaxf(m, sgate[n]);
    red[t] = m;
    __syncthreads();
    for (int s = 128; s; s >>= 1) { if (t < s) red[t] = fmaxf(red[t], red[t + s]); __syncthreads(); }
    float gmax = red[0];
    __syncthreads();

    float ssum = 0.f;
    for (int n = t; n < NPG; n += 256) {
        float e = expf(sgate[n] - gmax);
        sgate[n] = e;
        ssum += e;
    }
    red[t] = ssum;
    __syncthreads();
    for (int s = 128; s; s >>= 1) { if (t < s) red[t] += red[t + s]; __syncthreads(); }
    float z = red[0];
    __syncthreads();

    int d = t & 63, p = t >> 6;   // 4 partials per dim
    float acc = 0.f;
    for (int n = p; n < NPG; n += 4)
        acc += sgate[n] * H[(size_t)(g * NPG + n) * LD + d];
    red[t] = acc;
    __syncthreads();
    if (t < 64)
        out[g * 64 + t] = (red[t] + red[t + 64] + red[t + 128] + red[t + 192]) / z;
}

// ---------------- launch ----------------
extern "C" void kernel_launch(void* const* d_in, const int* in_sizes, int n_in,
                              void* d_out, int out_size) {
    const float* x   = (const float*)d_in[0];
    const int*   src = (const int*)d_in[1];
    const int*   dst = (const int*)d_in[2];
    // d_in[3] = node2graph (contiguous by construction; unused)
    const float* W0 = (const float*)d_in[4];
    const float* b0 = (const float*)d_in[5];
    const float* W1 = (const float*)d_in[6];
    const float* b1 = (const float*)d_in[7];
    const float* W2 = (const float*)d_in[8];
    const float* b2 = (const float*)d_in[9];
    const float* W3 = (const float*)d_in[10];
    const float* b3 = (const float*)d_in[11];
    const float* Wg = (const float*)d_in[12];
    const float* bg = (const float*)d_in[13];
    float* out = (float*)d_out;

    // opt-in dynamic smem for the 64-wide GEMM (73.7 KB)
    static int smem_set = 0;
    (void)smem_set;
    cudaFuncSetAttribute(k_gemm_relu<64>, cudaFuncAttributeMaxDynamicSharedMemorySize,
                         (3 * 64 * 64 + 32 * 3 * 64) * (int)sizeof(float));

    float* M0 = nullptr; float* M1 = nullptr; float* T1 = nullptr; float* T2 = nullptr;
    cudaGetSymbolAddress((void**)&M0, g_M0);
    cudaGetSymbolAddress((void**)&M1, g_M1);
    cudaGetSymbolAddress((void**)&T1, g_T1);
    cudaGetSymbolAddress((void**)&T2, g_T2);

    // ---- CSR build ----
    k_zero_deg<<<(NN + 255) / 256, 256>>>();
    k_deg<<<(EE + 255) / 256, 256>>>(dst);
    k_norm<<<(NN + 255) / 256, 256>>>();
    k_scan1<<<SCAN_NB, SCAN_BS>>>();
    k_scan2<<<1, 1024>>>();
    k_scan3<<<(NN + 255) / 256, 256>>>();
    k_fill<<<(EE + 255) / 256, 256>>>(src, dst);

    // ---- layer 0 (F=31) ----
    k_pad<<<(NN * LD + 255) / 256, 256>>>(x);
    dim3 sb(32, 8);
    int sgrid = (NN + 7) / 8;
    k_spmm<false><<<sgrid, sb>>>(M0, T1);
    k_spmm<false><<<sgrid, sb>>>(T1, T2);
    {
        constexpr int KK = 3 * IN_F;
        size_t sh = (KK * 64 + 32 * KK) * sizeof(float);
        k_gemm_relu<IN_F><<<NN / 32, 256, sh>>>(M0, T1, T2, W0, b0, M1);
    }

    // ---- layers 1..3 (F=64) ----
    {
        constexpr int KK = 3 * 64;
        size_t sh = (KK * 64 + 32 * KK) * sizeof(float);
        // layer 1: M1 -> M0
        k_spmm<true><<<sgrid, sb>>>(M1, T1);
        k_spmm<true><<<sgrid, sb>>>(T1, T2);
        k_gemm_relu<64><<<NN / 32, 256, sh>>>(M1, T1, T2, W1, b1, M0);
        // layer 2: M0 -> M1
        k_spmm<true><<<sgrid, sb>>>(M0, T1);
        k_spmm<true><<<sgrid, sb>>>(T1, T2);
        k_gemm_relu<64><<<NN / 32, 256, sh>>>(M0, T1, T2, W2, b2, M1);
        // layer 3: M1 -> M0
        k_spmm<true><<<sgrid, sb>>>(M1, T1);
        k_spmm<true><<<sgrid, sb>>>(T1, T2);
        k_gemm_relu<64><<<NN / 32, 256, sh>>>(M1, T1, T2, W3, b3, M0);
    }

    // ---- pooling ----
    k_pool<<<GG, 256>>>(M0, Wg, bg, out);
}

// round 3
// speedup vs baseline: 1.2559x; 1.2559x over previous
#include <cuda_runtime.h>
#include <cuda_bf16.h>
#include <math.h>
#include <stdint.h>

#define NN 160000
#define GG 800
#define NPG 200
#define EE 1280000
#define IN_F 31
#define HID 64
#define LD 64

#define SCAN_BS 512
#define SCAN_NB ((NN + SCAN_BS - 1) / SCAN_BS)   // 313

// ---------------- static device scratch (no allocation allowed) ----------------
__device__ int   g_deg[NN];
__device__ float g_norm[NN];
__device__ int   g_incl[NN];
__device__ int   g_bsums[1024];
__device__ int   g_rowptr[NN + 1];
__device__ int   g_cursor[NN];
__device__ int   g_col[EE];

__device__ float g_M0[NN * LD];
__device__ float g_M1[NN * LD];
__device__ float g_T1[NN * LD];
__device__ float g_T2[NN * LD];

// padded weights, tf32 hi/lo split, k-major: [4 layers][192 k][64 n]
__device__ uint32_t g_Wth[4 * 192 * 64];
__device__ uint32_t g_Wtl[4 * 192 * 64];

__device__ __forceinline__ uint32_t f2tf32(float f) {
    uint32_t r;
    asm("cvt.rna.tf32.f32 %0, %1;" : "=r"(r) : "f"(f));
    return r;
}

// ---------------- degree / norm ----------------
__global__ void k_zero_deg() {
    int i = blockIdx.x * blockDim.x + threadIdx.x;
    if (i < NN) g_deg[i] = 0;
}
__global__ void k_deg(const int* __restrict__ dst) {
    int i = blockIdx.x * blockDim.x + threadIdx.x;
    if (i < EE) atomicAdd(&g_deg[dst[i]], 1);
}
__global__ void k_norm() {
    int i = blockIdx.x * blockDim.x + threadIdx.x;
    if (i < NN) g_norm[i] = rsqrtf(fmaxf((float)g_deg[i], 1.0f));
}

// ---------------- scan ----------------
__global__ void k_scan1() {
    __shared__ int sh[SCAN_BS];
    int i = blockIdx.x * SCAN_BS + threadIdx.x;
    int v = (i < NN) ? g_deg[i] : 0;
    sh[threadIdx.x] = v;
    __syncthreads();
    for (int off = 1; off < SCAN_BS; off <<= 1) {
        int t = (threadIdx.x >= off) ? sh[threadIdx.x - off] : 0;
        __syncthreads();
        sh[threadIdx.x] += t;
        __syncthreads();
    }
    if (i < NN) g_incl[i] = sh[threadIdx.x];
    if (threadIdx.x == SCAN_BS - 1) g_bsums[blockIdx.x] = sh[threadIdx.x];
}
__global__ void k_scan2() {
    __shared__ int sh[1024];
    int t = threadIdx.x;
    int orig = (t < SCAN_NB) ? g_bsums[t] : 0;
    sh[t] = orig;
    __syncthreads();
    for (int off = 1; off < 1024; off <<= 1) {
        int v = (t >= off) ? sh[t - off] : 0;
        __syncthreads();
        sh[t] += v;
        __syncthreads();
    }
    if (t < SCAN_NB) g_bsums[t] = sh[t] - orig;
}
__global__ void k_scan3() {
    int i = blockIdx.x * blockDim.x + threadIdx.x;
    if (i < NN) {
        int ex = g_incl[i] - g_deg[i] + g_bsums[i / SCAN_BS];
        g_rowptr[i] = ex;
        g_cursor[i] = ex;
    }
    if (i == 0) g_rowptr[NN] = EE;
}
__global__ void k_fill(const int* __restrict__ src, const int* __restrict__ dst) {
    int i = blockIdx.x * blockDim.x + threadIdx.x;
    if (i < EE) {
        int p = atomicAdd(&g_cursor[dst[i]], 1);
        g_col[p] = src[i];
    }
}

// ---------------- pad x [N,31] -> M0 [N,64] ----------------
__global__ void k_pad(const float* __restrict__ x) {
    int i = blockIdx.x * blockDim.x + threadIdx.x;
    if (i < NN * LD) {
        int node = i >> 6, c = i & 63;
        g_M0[i] = (c < IN_F) ? x[node * IN_F + c] : 0.0f;
    }
}

// ---------------- SpMM hop ----------------
template <bool TWO>
__global__ void k_spmm(const float* __restrict__ Hin, float* __restrict__ Hout) {
    int node = blockIdx.x * blockDim.y + threadIdx.y;
    if (node >= NN) return;
    int lane = threadIdx.x;
    int s = g_rowptr[node], e = g_rowptr[node + 1];
    float a0 = 0.f, a1 = 0.f;
    for (int j = s; j < e; j++) {
        int u = g_col[j];
        float nu = __ldg(&g_norm[u]);
        a0 += nu * __ldg(&Hin[u * LD + lane]);
        if (TWO) a1 += nu * __ldg(&Hin[u * LD + lane + 32]);
    }
    float nv = g_norm[node];
    Hout[node * LD + lane] = nv * a0;
    if (TWO) Hout[node * LD + lane + 32] = nv * a1;
    else     Hout[node * LD + lane + 32] = 0.0f;
}

// ---------------- weight prep: pad (layer0), tf32 hi/lo split, [k][n] ----------------
__global__ void k_wprep(const float* __restrict__ W0, const float* __restrict__ W1,
                        const float* __restrict__ W2, const float* __restrict__ W3) {
    int i = blockIdx.x * blockDim.x + threadIdx.x;
    if (i >= 4 * 192 * 64) return;
    int l = i / 12288;
    int rem = i - l * 12288;
    int k = rem >> 6;
    int n = rem & 63;
    float v;
    if (l == 0) {
        int hop = k >> 6, c = k & 63;
        v = (c < IN_F) ? W0[(hop * IN_F + c) * 64 + n] : 0.0f;
    } else if (l == 1) v = W1[k * 64 + n];
    else if (l == 2)   v = W2[k * 64 + n];
    else               v = W3[k * 64 + n];
    uint32_t hi = f2tf32(v);
    float hif = __uint_as_float(hi);
    uint32_t lo = f2tf32(v - hif);
    g_Wth[i] = hi;
    g_Wtl[i] = lo;
}

// ---------------- tensor-core tf32-split GEMM + bias + ReLU ----------------
// Out[128, 64] = relu( concat(H0,H1,H2)[128, 192] @ W[192, 64] + bias )
// mma.sync.m16n8k8 tf32, 3-pass split: AhiBhi + AloBhi + AhiBlo
#define A_STR 36
#define B_STR 72
// smem (uint32 units): bias 64 | Ahi 128*36 | Alo 128*36 | Bhi 32*72 | Blo 32*72
#define SMO_BIAS 0
#define SMO_AHI 64
#define SMO_ALO (SMO_AHI + 128 * A_STR)
#define SMO_BHI (SMO_ALO + 128 * A_STR)
#define SMO_BLO (SMO_BHI + 32 * B_STR)
#define GEMM_SMEM_U32 (SMO_BLO + 32 * B_STR)
#define GEMM_SMEM_B (GEMM_SMEM_U32 * 4)

__device__ __forceinline__ void mma_tf32(float* c, uint32_t a0, uint32_t a1,
                                         uint32_t a2, uint32_t a3,
                                         uint32_t b0, uint32_t b1) {
    asm volatile(
        "mma.sync.aligned.m16n8k8.row.col.f32.tf32.tf32.f32 "
        "{%0,%1,%2,%3}, {%4,%5,%6,%7}, {%8,%9}, {%0,%1,%2,%3};"
        : "+f"(c[0]), "+f"(c[1]), "+f"(c[2]), "+f"(c[3])
        : "r"(a0), "r"(a1), "r"(a2), "r"(a3), "r"(b0), "r"(b1));
}

__global__ void __launch_bounds__(256) k_gemm_tc(
    const float* __restrict__ H0, const float* __restrict__ H1,
    const float* __restrict__ H2, const uint32_t* __restrict__ Wth,
    const uint32_t* __restrict__ Wtl, const float* __restrict__ bias,
    float* __restrict__ Out)
{
    extern __shared__ __align__(16) uint32_t sm[];
    uint32_t* Ahi = sm + SMO_AHI;
    uint32_t* Alo = sm + SMO_ALO;
    uint32_t* Bhi = sm + SMO_BHI;
    uint32_t* Blo = sm + SMO_BLO;
    float* sbias = (float*)(sm + SMO_BIAS);

    int tid = threadIdx.x;
    int warp = tid >> 5, lane = tid & 31;
    int row0 = blockIdx.x * 128;
    if (tid < 16) ((float4*)sbias)[tid] = ((const float4*)bias)[tid];

    float acc[8][4];
#pragma unroll
    for (int nt = 0; nt < 8; nt++)
#pragma unroll
        for (int j = 0; j < 4; j++) acc[nt][j] = 0.f;

    const float* bufs[3] = {H0, H1, H2};
    int lg = lane >> 2, lm = lane & 3;

    for (int c = 0; c < 6; c++) {
        __syncthreads();
        // ---- stage A chunk (128 rows x 32 k), hi/lo split ----
        {
            const float* H = bufs[c >> 1];
            int half = (c & 1) * 32;
#pragma unroll
            for (int it = 0; it < 4; it++) {
                int idx = tid + it * 256;           // 0..1023 float4s
                int r = idx >> 3, c4 = idx & 7;
                float4 v = *(const float4*)&H[(row0 + r) * 64 + half + c4 * 4];
                uint4 hi, lo;
                hi.x = f2tf32(v.x); lo.x = f2tf32(v.x - __uint_as_float(hi.x));
                hi.y = f2tf32(v.y); lo.y = f2tf32(v.y - __uint_as_float(hi.y));
                hi.z = f2tf32(v.z); lo.z = f2tf32(v.z - __uint_as_float(hi.z));
                hi.w = f2tf32(v.w); lo.w = f2tf32(v.w - __uint_as_float(hi.w));
                int off = r * A_STR + c4 * 4;
                *(uint4*)(Ahi + off) = hi;
                *(uint4*)(Alo + off) = lo;
            }
        }
        // ---- stage B chunk (32 k x 64 n) hi/lo ----
        {
#pragma unroll
            for (int it = 0; it < 2; it++) {
                int idx = tid + it * 256;           // 0..511 uint4s
                int k = idx >> 4, n4 = idx & 15;
                int goff = (c * 32 + k) * 64 + n4 * 4;
                uint4 vh = *(const uint4*)&Wth[goff];
                uint4 vl = *(const uint4*)&Wtl[goff];
                int off = k * B_STR + n4 * 4;
                *(uint4*)(Bhi + off) = vh;
                *(uint4*)(Blo + off) = vl;
            }
        }
        __syncthreads();

        int rA = warp * 16 + lg;
#pragma unroll
        for (int ks = 0; ks < 4; ks++) {
            int kk = ks * 8 + lm;
            uint32_t ah0 = Ahi[rA * A_STR + kk];
            uint32_t ah1 = Ahi[(rA + 8) * A_STR + kk];
            uint32_t ah2 = Ahi[rA * A_STR + kk + 4];
            uint32_t ah3 = Ahi[(rA + 8) * A_STR + kk + 4];
            uint32_t al0 = Alo[rA * A_STR + kk];
            uint32_t al1 = Alo[(rA + 8) * A_STR + kk];
            uint32_t al2 = Alo[rA * A_STR + kk + 4];
            uint32_t al3 = Alo[(rA + 8) * A_STR + kk + 4];
#pragma unroll
            for (int nt = 0; nt < 8; nt++) {
                int col = nt * 8 + lg;
                int kb = ks * 8 + lm;
                uint32_t bh0 = Bhi[kb * B_STR + col];
                uint32_t bh1 = Bhi[(kb + 4) * B_STR + col];
                uint32_t bl0 = Blo[kb * B_STR + col];
                uint32_t bl1 = Blo[(kb + 4) * B_STR + col];
                mma_tf32(acc[nt], ah0, ah1, ah2, ah3, bh0, bh1);
                mma_tf32(acc[nt], al0, al1, al2, al3, bh0, bh1);
                mma_tf32(acc[nt], ah0, ah1, ah2, ah3, bl0, bl1);
            }
        }
    }

    // ---- epilogue: bias + relu + store ----
    int r = row0 + warp * 16 + lg;
    int cb = lm * 2;
#pragma unroll
    for (int nt = 0; nt < 8; nt++) {
        int col = nt * 8 + cb;
        float b0 = sbias[col], b1 = sbias[col + 1];
        float2 o0, o1;
        o0.x = fmaxf(acc[nt][0] + b0, 0.f);
        o0.y = fmaxf(acc[nt][1] + b1, 0.f);
        o1.x = fmaxf(acc[nt][2] + b0, 0.f);
        o1.y = fmaxf(acc[nt][3] + b1, 0.f);
        *(float2*)&Out[(size_t)r * 64 + col] = o0;
        *(float2*)&Out[(size_t)(r + 8) * 64 + col] = o1;
    }
}

// ---------------- per-graph attention pooling ----------------
__global__ void k_pool(const float* __restrict__ H, const float* __restrict__ Wg,
                       const float* __restrict__ bg, float* __restrict__ out) {
    int g = blockIdx.x;
    __shared__ float sWg[64];
    __shared__ float sgate[NPG];
    __shared__ float red[256];
    int t = threadIdx.x;
    if (t < 64) sWg[t] = Wg[t];
    __syncthreads();

    int lane = t & 31, w = t >> 5;
    float bgv = bg[0];
    for (int n = w; n < NPG; n += 8) {
        const float* hp = H + (size_t)(g * NPG + n) * LD;
        float v = hp[lane] * sWg[lane] + hp[lane + 32] * sWg[lane + 32];
#pragma unroll
        for (int o = 16; o; o >>= 1) v += __shfl_xor_sync(0xffffffffu, v, o);
        if (lane == 0) sgate[n] = v + bgv;
    }
    __syncthreads();

    float m = -INFINITY;
    for (int n = t; n < NPG; n += 256) m = fmaxf(m, sgate[n]);
    red[t] = m;
    __syncthreads();
    for (int s = 128; s; s >>= 1) { if (t < s) red[t] = fmaxf(red[t], red[t + s]); __syncthreads(); }
    float gmax = red[0];
    __syncthreads();

    float ssum = 0.f;
    for (int n = t; n < NPG; n += 256) {
        float e = expf(sgate[n] - gmax);
        sgate[n] = e;
        ssum += e;
    }
    red[t] = ssum;
    __syncthreads();
    for (int s = 128; s; s >>= 1) { if (t < s) red[t] += red[t + s]; __syncthreads(); }
    float z = red[0];
    __syncthreads();

    int d = t & 63, p = t >> 6;
    float acc = 0.f;
    for (int n = p; n < NPG; n += 4)
        acc += sgate[n] * H[(size_t)(g * NPG + n) * LD + d];
    red[t] = acc;
    __syncthreads();
    if (t < 64)
        out[g * 64 + t] = (red[t] + red[t + 64] + red[t + 128] + red[t + 192]) / z;
}

// ---------------- launch ----------------
extern "C" void kernel_launch(void* const* d_in, const int* in_sizes, int n_in,
                              void* d_out, int out_size) {
    const float* x   = (const float*)d_in[0];
    const int*   src = (const int*)d_in[1];
    const int*   dst = (const int*)d_in[2];
    const float* W0 = (const float*)d_in[4];
    const float* b0 = (const float*)d_in[5];
    const float* W1 = (const float*)d_in[6];
    const float* b1 = (const float*)d_in[7];
    const float* W2 = (const float*)d_in[8];
    const float* b2 = (const float*)d_in[9];
    const float* W3 = (const float*)d_in[10];
    const float* b3 = (const float*)d_in[11];
    const float* Wg = (const float*)d_in[12];
    const float* bg = (const float*)d_in[13];
    float* out = (float*)d_out;

    cudaFuncSetAttribute(k_gemm_tc, cudaFuncAttributeMaxDynamicSharedMemorySize, GEMM_SMEM_B);

    float *M0, *M1, *T1, *T2;
    uint32_t *Wth, *Wtl;
    cudaGetSymbolAddress((void**)&M0, g_M0);
    cudaGetSymbolAddress((void**)&M1, g_M1);
    cudaGetSymbolAddress((void**)&T1, g_T1);
    cudaGetSymbolAddress((void**)&T2, g_T2);
    cudaGetSymbolAddress((void**)&Wth, g_Wth);
    cudaGetSymbolAddress((void**)&Wtl, g_Wtl);

    // ---- CSR build ----
    k_zero_deg<<<(NN + 255) / 256, 256>>>();
    k_deg<<<(EE + 255) / 256, 256>>>(dst);
    k_norm<<<(NN + 255) / 256, 256>>>();
    k_scan1<<<SCAN_NB, SCAN_BS>>>();
    k_scan2<<<1, 1024>>>();
    k_scan3<<<(NN + 255) / 256, 256>>>();
    k_fill<<<(EE + 255) / 256, 256>>>(src, dst);

    // ---- weight prep ----
    k_wprep<<<(4 * 192 * 64 + 255) / 256, 256>>>(W0, W1, W2, W3);

    // ---- layer 0 ----
    k_pad<<<(NN * LD + 255) / 256, 256>>>(x);
    dim3 sb(32, 8);
    int sgrid = (NN + 7) / 8;
    const int ggrid = NN / 128;  // 1250

    k_spmm<false><<<sgrid, sb>>>(M0, T1);
    k_spmm<false><<<sgrid, sb>>>(T1, T2);
    k_gemm_tc<<<ggrid, 256, GEMM_SMEM_B>>>(M0, T1, T2, Wth + 0 * 12288, Wtl + 0 * 12288, b0, M1);

    // ---- layer 1 ----
    k_spmm<true><<<sgrid, sb>>>(M1, T1);
    k_spmm<true><<<sgrid, sb>>>(T1, T2);
    k_gemm_tc<<<ggrid, 256, GEMM_SMEM_B>>>(M1, T1, T2, Wth + 1 * 12288, Wtl + 1 * 12288, b1, M0);

    // ---- layer 2 ----
    k_spmm<true><<<sgrid, sb>>>(M0, T1);
    k_spmm<true><<<sgrid, sb>>>(T1, T2);
    k_gemm_tc<<<ggrid, 256, GEMM_SMEM_B>>>(M0, T1, T2, Wth + 2 * 12288, Wtl + 2 * 12288, b2, M1);

    // ---- layer 3 ----
    k_spmm<true><<<sgrid, sb>>>(M1, T1);
    k_spmm<true><<<sgrid, sb>>>(T1, T2);
    k_gemm_tc<<<ggrid, 256, GEMM_SMEM_B>>>(M1, T1, T2, Wth + 3 * 12288, Wtl + 3 * 12288, b3, M0);

    // ---- pooling ----
    k_pool<<<GG, 256>>>(M0, Wg, bg, out);
}

// round 4
// speedup vs baseline: 1.3684x; 1.0896x over previous
#include <cuda_runtime.h>
#include <cuda_bf16.h>
#include <math.h>
#include <stdint.h>

#define NN 160000
#define GG 800
#define NPG 200
#define EE 1280000
#define IN_F 31
#define HID 64
#define LD 64

#define SCAN_BS 512
#define SCAN_NB ((NN + SCAN_BS - 1) / SCAN_BS)   // 313

// ---------------- static device scratch ----------------
__device__ int   g_deg[NN];
__device__ float g_norm[NN];
__device__ int   g_incl[NN];
__device__ int   g_bsums[1024];
__device__ int   g_rowptr[NN + 1];
__device__ int   g_cursor[NN];
__device__ int   g_col[EE];

__device__ float g_M0[NN * LD];
__device__ float g_M1[NN * LD];
__device__ float g_T1[NN * LD];
__device__ float g_T2[NN * LD];

// weights, bf16 hi/lo split, packed k-pairs: [4 layers][64 n][96 kp]
__device__ uint32_t g_Wbh[4 * 64 * 96];
__device__ uint32_t g_Wbl[4 * 64 * 96];

// pack (x -> low half, y -> high half) as bf16x2
__device__ __forceinline__ uint32_t pack_bf16x2(float x, float y) {
    uint32_t r;
    asm("cvt.rn.bf16x2.f32 %0, %1, %2;" : "=r"(r) : "f"(y), "f"(x));
    return r;
}

// ---------------- degree ----------------
__global__ void k_zero_deg() {
    int i = blockIdx.x * blockDim.x + threadIdx.x;
    if (i < NN) g_deg[i] = 0;
}
__global__ void k_deg(const int* __restrict__ dst) {
    int i = blockIdx.x * blockDim.x + threadIdx.x;
    if (i < EE) atomicAdd(&g_deg[dst[i]], 1);
}

// ---------------- scan ----------------
__global__ void k_scan1() {
    __shared__ int sh[SCAN_BS];
    int i = blockIdx.x * SCAN_BS + threadIdx.x;
    int v = (i < NN) ? g_deg[i] : 0;
    sh[threadIdx.x] = v;
    __syncthreads();
    for (int off = 1; off < SCAN_BS; off <<= 1) {
        int t = (threadIdx.x >= off) ? sh[threadIdx.x - off] : 0;
        __syncthreads();
        sh[threadIdx.x] += t;
        __syncthreads();
    }
    if (i < NN) g_incl[i] = sh[threadIdx.x];
    if (threadIdx.x == SCAN_BS - 1) g_bsums[blockIdx.x] = sh[threadIdx.x];
}
__global__ void k_scan2() {
    __shared__ int sh[1024];
    int t = threadIdx.x;
    int orig = (t < SCAN_NB) ? g_bsums[t] : 0;
    sh[t] = orig;
    __syncthreads();
    for (int off = 1; off < 1024; off <<= 1) {
        int v = (t >= off) ? sh[t - off] : 0;
        __syncthreads();
        sh[t] += v;
        __syncthreads();
    }
    if (t < SCAN_NB) g_bsums[t] = sh[t] - orig;
}
__global__ void k_scan3() {   // also computes norm
    int i = blockIdx.x * blockDim.x + threadIdx.x;
    if (i < NN) {
        int d = g_deg[i];
        int ex = g_incl[i] - d + g_bsums[i / SCAN_BS];
        g_rowptr[i] = ex;
        g_cursor[i] = ex;
        g_norm[i] = rsqrtf(fmaxf((float)d, 1.0f));
    }
    if (i == 0) g_rowptr[NN] = EE;
}
__global__ void k_fill(const int* __restrict__ src, const int* __restrict__ dst) {
    int i = blockIdx.x * blockDim.x + threadIdx.x;
    if (i < EE) {
        int p = atomicAdd(&g_cursor[dst[i]], 1);
        g_col[p] = src[i];
    }
}

// ---------------- pad x [N,31] -> M0 [N,64] ----------------
__global__ void k_pad(const float* __restrict__ x) {
    int i = blockIdx.x * blockDim.x + threadIdx.x;
    if (i < NN * LD) {
        int node = i >> 6, c = i & 63;
        g_M0[i] = (c < IN_F) ? x[node * IN_F + c] : 0.0f;
    }
}

// ---------------- SpMM hop: float4 lanes, multi-edge per warp ----------------
// C4 = number of float4 column-groups (16 = full 64 cols, 8 = lower 32 cols)
template <int C4>
__global__ void __launch_bounds__(256) k_spmm(const float* __restrict__ Hin,
                                              float* __restrict__ Hout) {
    constexpr int EP = 32 / C4;   // edges in parallel: 2 or 4
    int node = blockIdx.x * 8 + (threadIdx.x >> 5);
    if (node >= NN) return;
    int lane = threadIdx.x & 31;
    int grp = lane / C4;
    int q = lane % C4;
    int s = g_rowptr[node], e = g_rowptr[node + 1];
    float4 acc = make_float4(0.f, 0.f, 0.f, 0.f);

    int j = s + grp;
    for (; j + EP < e; j += 2 * EP) {
        int u0 = __ldg(&g_col[j]);
        int u1 = __ldg(&g_col[j + EP]);
        float n0 = __ldg(&g_norm[u0]);
        float n1 = __ldg(&g_norm[u1]);
        float4 v0 = *(const float4*)&Hin[(size_t)u0 * 64 + q * 4];
        float4 v1 = *(const float4*)&Hin[(size_t)u1 * 64 + q * 4];
        acc.x += n0 * v0.x; acc.y += n0 * v0.y;
        acc.z += n0 * v0.z; acc.w += n0 * v0.w;
        acc.x += n1 * v1.x; acc.y += n1 * v1.y;
        acc.z += n1 * v1.z; acc.w += n1 * v1.w;
    }
    if (j < e) {
        int u = __ldg(&g_col[j]);
        float nu = __ldg(&g_norm[u]);
        float4 v = *(const float4*)&Hin[(size_t)u * 64 + q * 4];
        acc.x += nu * v.x; acc.y += nu * v.y;
        acc.z += nu * v.z; acc.w += nu * v.w;
    }
#pragma unroll
    for (int off = 16; off >= C4; off >>= 1) {
        acc.x += __shfl_xor_sync(0xffffffffu, acc.x, off);
        acc.y += __shfl_xor_sync(0xffffffffu, acc.y, off);
        acc.z += __shfl_xor_sync(0xffffffffu, acc.z, off);
        acc.w += __shfl_xor_sync(0xffffffffu, acc.w, off);
    }
    if (lane < C4) {
        float nv = g_norm[node];
        acc.x *= nv; acc.y *= nv; acc.z *= nv; acc.w *= nv;
        *(float4*)&Hout[(size_t)node * 64 + q * 4] = acc;
        if (C4 == 8)
            *(float4*)&Hout[(size_t)node * 64 + 32 + q * 4] =
                make_float4(0.f, 0.f, 0.f, 0.f);
    }
}

// ---------------- weight prep: transpose/pad -> bf16 hi/lo packed k-pairs ----------------
__global__ void k_wprep(const float* __restrict__ W0, const float* __restrict__ W1,
                        const float* __restrict__ W2, const float* __restrict__ W3) {
    int i = blockIdx.x * blockDim.x + threadIdx.x;
    if (i >= 4 * 64 * 96) return;
    int l = i / 6144;
    int rem = i - l * 6144;
    int n = rem / 96;
    int kp = rem - n * 96;
    float v[2];
#pragma unroll
    for (int t = 0; t < 2; t++) {
        int k = kp * 2 + t;
        if (l == 0) {
            int hop = k >> 6, c = k & 63;
            v[t] = (c < IN_F) ? W0[(hop * IN_F + c) * 64 + n] : 0.0f;
        } else if (l == 1) v[t] = W1[k * 64 + n];
        else if (l == 2)   v[t] = W2[k * 64 + n];
        else               v[t] = W3[k * 64 + n];
    }
    uint32_t h = pack_bf16x2(v[0], v[1]);
    float xh = __uint_as_float(h << 16);
    float yh = __uint_as_float(h & 0xffff0000u);
    uint32_t lo = pack_bf16x2(v[0] - xh, v[1] - yh);
    g_Wbh[i] = h;
    g_Wbl[i] = lo;
}

// ---------------- bf16-split tensor-core GEMM + bias + ReLU ----------------
// Out[128, 64] = relu( concat(H0,H1,H2)[128, 192] @ W[192, 64] + bias )
// mma.m16n8k16 bf16, 3 terms: AhiBhi + AloBhi + AhiBlo
#define ASTR 20
#define BSTR 20

__device__ __forceinline__ void mma_bf16(float* c, uint32_t a0, uint32_t a1,
                                         uint32_t a2, uint32_t a3,
                                         uint32_t b0, uint32_t b1) {
    asm volatile(
        "mma.sync.aligned.m16n8k16.row.col.f32.bf16.bf16.f32 "
        "{%0,%1,%2,%3}, {%4,%5,%6,%7}, {%8,%9}, {%0,%1,%2,%3};"
        : "+f"(c[0]), "+f"(c[1]), "+f"(c[2]), "+f"(c[3])
        : "r"(a0), "r"(a1), "r"(a2), "r"(a3), "r"(b0), "r"(b1));
}

__global__ void __launch_bounds__(256) k_gemm_tc(
    const float* __restrict__ H0, const float* __restrict__ H1,
    const float* __restrict__ H2, const uint32_t* __restrict__ Wbh,
    const uint32_t* __restrict__ Wbl, const float* __restrict__ bias,
    float* __restrict__ Out)
{
    __shared__ float sbias[64];
    __shared__ uint32_t Ahi[128 * ASTR];
    __shared__ uint32_t Alo[128 * ASTR];
    __shared__ uint32_t Bhi[64 * BSTR];
    __shared__ uint32_t Blo[64 * BSTR];

    int tid = threadIdx.x;
    int warp = tid >> 5, lane = tid & 31;
    int lg = lane >> 2, lm = lane & 3;
    int row0 = blockIdx.x * 128;
    if (tid < 64) sbias[tid] = bias[tid];

    float acc[8][4];
#pragma unroll
    for (int nt = 0; nt < 8; nt++)
#pragma unroll
        for (int jj = 0; jj < 4; jj++) acc[nt][jj] = 0.f;

    const float* bufs[3] = {H0, H1, H2};

    for (int c = 0; c < 6; c++) {
        __syncthreads();
        // ---- stage A chunk (128 rows x 32 k) as bf16 hi/lo k-pairs ----
        {
            const float* H = bufs[c >> 1];
            int half = (c & 1) * 32;
#pragma unroll
            for (int it = 0; it < 4; it++) {
                int idx = tid + it * 256;          // 0..1023 float4s
                int r = idx >> 3, q = idx & 7;     // q: float4 within 32 floats
                float4 v = *(const float4*)&H[(size_t)(row0 + r) * 64 + half + q * 4];
                uint32_t h0 = pack_bf16x2(v.x, v.y);
                uint32_t h1 = pack_bf16x2(v.z, v.w);
                float xh = __uint_as_float(h0 << 16);
                float yh = __uint_as_float(h0 & 0xffff0000u);
                float zh = __uint_as_float(h1 << 16);
                float wh = __uint_as_float(h1 & 0xffff0000u);
                uint32_t l0 = pack_bf16x2(v.x - xh, v.y - yh);
                uint32_t l1 = pack_bf16x2(v.z - zh, v.w - wh);
                int off = r * ASTR + q * 2;
                Ahi[off] = h0; Ahi[off + 1] = h1;
                Alo[off] = l0; Alo[off + 1] = l1;
            }
        }
        // ---- stage B chunk (64 n x 16 kp) ----
        {
#pragma unroll
            for (int it = 0; it < 4; it++) {
                int idx = tid + it * 256;          // 0..1023
                int n = idx >> 4, kpl = idx & 15;
                int goff = n * 96 + c * 16 + kpl;
                Bhi[n * BSTR + kpl] = Wbh[goff];
                Blo[n * BSTR + kpl] = Wbl[goff];
            }
        }
        __syncthreads();

        int rA = warp * 16 + lg;
#pragma unroll
        for (int ks = 0; ks < 2; ks++) {
            int kb = ks * 8 + lm;
            uint32_t ah0 = Ahi[rA * ASTR + kb];
            uint32_t ah1 = Ahi[(rA + 8) * ASTR + kb];
            uint32_t ah2 = Ahi[rA * ASTR + kb + 4];
            uint32_t ah3 = Ahi[(rA + 8) * ASTR + kb + 4];
            uint32_t al0 = Alo[rA * ASTR + kb];
            uint32_t al1 = Alo[(rA + 8) * ASTR + kb];
            uint32_t al2 = Alo[rA * ASTR + kb + 4];
            uint32_t al3 = Alo[(rA + 8) * ASTR + kb + 4];
#pragma unroll
            for (int nt = 0; nt < 8; nt++) {
                int col = nt * 8 + lg;
                uint32_t bh0 = Bhi[col * BSTR + kb];
                uint32_t bh1 = Bhi[col * BSTR + kb + 4];
                uint32_t bl0 = Blo[col * BSTR + kb];
                uint32_t bl1 = Blo[col * BSTR + kb + 4];
                mma_bf16(acc[nt], ah0, ah1, ah2, ah3, bh0, bh1);
                mma_bf16(acc[nt], al0, al1, al2, al3, bh0, bh1);
                mma_bf16(acc[nt], ah0, ah1, ah2, ah3, bl0, bl1);
            }
        }
    }

    // ---- epilogue: bias + relu + store ----
    int r = row0 + warp * 16 + lg;
    int cb = lm * 2;
#pragma unroll
    for (int nt = 0; nt < 8; nt++) {
        int col = nt * 8 + cb;
        float b0 = sbias[col], b1 = sbias[col + 1];
        float2 o0, o1;
        o0.x = fmaxf(acc[nt][0] + b0, 0.f);
        o0.y = fmaxf(acc[nt][1] + b1, 0.f);
        o1.x = fmaxf(acc[nt][2] + b0, 0.f);
        o1.y = fmaxf(acc[nt][3] + b1, 0.f);
        *(float2*)&Out[(size_t)r * 64 + col] = o0;
        *(float2*)&Out[(size_t)(r + 8) * 64 + col] = o1;
    }
}

// ---------------- per-graph attention pooling ----------------
__global__ void k_pool(const float* __restrict__ H, const float* __restrict__ Wg,
                       const float* __restrict__ bg, float* __restrict__ out) {
    int g = blockIdx.x;
    __shared__ float sWg[64];
    __shared__ float sgate[NPG];
    __shared__ float red[256];
    int t = threadIdx.x;
    if (t < 64) sWg[t] = Wg[t];
    __syncthreads();

    int lane = t & 31, w = t >> 5;
    float bgv = bg[0];
    for (int n = w; n < NPG; n += 8) {
        const float* hp = H + (size_t)(g * NPG + n) * LD;
        float v = hp[lane] * sWg[lane] + hp[lane + 32] * sWg[lane + 32];
#pragma unroll
        for (int o = 16; o; o >>= 1) v += __shfl_xor_sync(0xffffffffu, v, o);
        if (lane == 0) sgate[n] = v + bgv;
    }
    __syncthreads();

    float m = -INFINITY;
    for (int n = t; n < NPG; n += 256) m = fmaxf(m, sgate[n]);
    red[t] = m;
    __syncthreads();
    for (int s = 128; s; s >>= 1) { if (t < s) red[t] = fmaxf(red[t], red[t + s]); __syncthreads(); }
    float gmax = red[0];
    __syncthreads();

    float ssum = 0.f;
    for (int n = t; n < NPG; n += 256) {
        float e = expf(sgate[n] - gmax);
        sgate[n] = e;
        ssum += e;
    }
    red[t] = ssum;
    __syncthreads();
    for (int s = 128; s; s >>= 1) { if (t < s) red[t] += red[t + s]; __syncthreads(); }
    float z = red[0];
    __syncthreads();

    int d = t & 63, p = t >> 6;
    float acc = 0.f;
    for (int n = p; n < NPG; n += 4)
        acc += sgate[n] * H[(size_t)(g * NPG + n) * LD + d];
    red[t] = acc;
    __syncthreads();
    if (t < 64)
        out[g * 64 + t] = (red[t] + red[t + 64] + red[t + 128] + red[t + 192]) / z;
}

// ---------------- launch ----------------
extern "C" void kernel_launch(void* const* d_in, const int* in_sizes, int n_in,
                              void* d_out, int out_size) {
    const float* x   = (const float*)d_in[0];
    const int*   src = (const int*)d_in[1];
    const int*   dst = (const int*)d_in[2];
    const float* W0 = (const float*)d_in[4];
    const float* b0 = (const float*)d_in[5];
    const float* W1 = (const float*)d_in[6];
    const float* b1 = (const float*)d_in[7];
    const float* W2 = (const float*)d_in[8];
    const float* b2 = (const float*)d_in[9];
    const float* W3 = (const float*)d_in[10];
    const float* b3 = (const float*)d_in[11];
    const float* Wg = (const float*)d_in[12];
    const float* bg = (const float*)d_in[13];
    float* out = (float*)d_out;

    float *M0, *M1, *T1, *T2;
    uint32_t *Wbh, *Wbl;
    cudaGetSymbolAddress((void**)&M0, g_M0);
    cudaGetSymbolAddress((void**)&M1, g_M1);
    cudaGetSymbolAddress((void**)&T1, g_T1);
    cudaGetSymbolAddress((void**)&T2, g_T2);
    cudaGetSymbolAddress((void**)&Wbh, g_Wbh);
    cudaGetSymbolAddress((void**)&Wbl, g_Wbl);

    // ---- CSR build ----
    k_zero_deg<<<(NN + 255) / 256, 256>>>();
    k_deg<<<(EE + 255) / 256, 256>>>(dst);
    k_scan1<<<SCAN_NB, SCAN_BS>>>();
    k_scan2<<<1, 1024>>>();
    k_scan3<<<(NN + 255) / 256, 256>>>();
    k_fill<<<(EE + 255) / 256, 256>>>(src, dst);

    // ---- weight prep ----
    k_wprep<<<(4 * 64 * 96 + 255) / 256, 256>>>(W0, W1, W2, W3);

    // ---- layer 0 ----
    k_pad<<<(NN * LD + 255) / 256, 256>>>(x);
    const int sgrid = NN / 8;     // 20000
    const int ggrid = NN / 128;   // 1250

    k_spmm<8><<<sgrid, 256>>>(M0, T1);
    k_spmm<8><<<sgrid, 256>>>(T1, T2);
    k_gemm_tc<<<ggrid, 256>>>(M0, T1, T2, Wbh + 0 * 6144, Wbl + 0 * 6144, b0, M1);

    // ---- layer 1 ----
    k_spmm<16><<<sgrid, 256>>>(M1, T1);
    k_spmm<16><<<sgrid, 256>>>(T1, T2);
    k_gemm_tc<<<ggrid, 256>>>(M1, T1, T2, Wbh + 1 * 6144, Wbl + 1 * 6144, b1, M0);

    // ---- layer 2 ----
    k_spmm<16><<<sgrid, 256>>>(M0, T1);
    k_spmm<16><<<sgrid, 256>>>(T1, T2);
    k_gemm_tc<<<ggrid, 256>>>(M0, T1, T2, Wbh + 2 * 6144, Wbl + 2 * 6144, b2, M1);

    // ---- layer 3 ----
    k_spmm<16><<<sgrid, 256>>>(M1, T1);
    k_spmm<16><<<sgrid, 256>>>(T1, T2);
    k_gemm_tc<<<ggrid, 256>>>(M1, T1, T2, Wbh + 3 * 6144, Wbl + 3 * 6144, b3, M0);

    // ---- pooling ----
    k_pool<<<GG, 256>>>(M0, Wg, bg, out);
}

// round 5
// speedup vs baseline: 1.4458x; 1.0566x over previous
#include <cuda_runtime.h>
#include <cuda_bf16.h>
#include <math.h>
#include <stdint.h>

#define NN 160000
#define GG 800
#define NPG 200
#define EE 1280000
#define IN_F 31
#define HID 64
#define LD 64

#define SCAN_BS 512
#define SCAN_NB ((NN + SCAN_BS - 1) / SCAN_BS)   // 313

// ---------------- static device scratch ----------------
__device__ int   g_deg[NN];
__device__ float g_norm[NN];
__device__ int   g_incl[NN];
__device__ int   g_bsums[1024];
__device__ int   g_rowptr[NN + 1];
__device__ int   g_cursor[NN];
__device__ int   g_col[EE];

// feature buffers: packed words [lo_bf16 (hi16) | hi_bf16 (lo16)]
__device__ uint32_t g_M0[NN * LD];
__device__ uint32_t g_M1[NN * LD];
__device__ uint32_t g_T1[NN * LD];
__device__ uint32_t g_T2[NN * LD];

// weights bf16 hi/lo, pair-interleaved: word idx = (((l*64+n)*6+c)*8+P)*2+half
__device__ uint32_t g_Wbh[4 * 64 * 96];
__device__ uint32_t g_Wbl[4 * 64 * 96];

// pack (x -> low half, y -> high half) as bf16x2
__device__ __forceinline__ uint32_t pack_bf16x2(float x, float y) {
    uint32_t r;
    asm("cvt.rn.bf16x2.f32 %0, %1, %2;" : "=r"(r) : "f"(y), "f"(x));
    return r;
}
// pack fp32 -> [lo16|hi16] split word
__device__ __forceinline__ uint32_t packf(float v) {
    uint32_t h = pack_bf16x2(v, 0.0f);
    float hf = __uint_as_float(h << 16);
    return pack_bf16x2(v, v - hf);
}
// reconstruct fp32 from split word
__device__ __forceinline__ float recon(uint32_t w) {
    return __uint_as_float(w << 16) + __uint_as_float(w & 0xffff0000u);
}

// ---------------- fused: degree count + pad/pack x + weight prep ----------------
#define DEG_NB 5000
#define PAD_NB 40000
#define WPREP_NB 96

__global__ void k_fused(const int* __restrict__ dst, const float* __restrict__ x,
                        const float* __restrict__ W0, const float* __restrict__ W1,
                        const float* __restrict__ W2, const float* __restrict__ W3) {
    int b = blockIdx.x, t = threadIdx.x;
    if (b < DEG_NB) {
        int i = b * 256 + t;
        if (i < EE) atomicAdd(&g_deg[dst[i]], 1);
    } else if (b < DEG_NB + PAD_NB) {
        int idx = (b - DEG_NB) * 256 + t;           // < NN*64
        int node = idx >> 6, c = idx & 63;
        g_M0[idx] = (c < IN_F) ? packf(x[node * IN_F + c]) : 0u;
    } else {
        int idx = (b - DEG_NB - PAD_NB) * 256 + t;  // < 4*64*96
        int l = idx / 6144;
        int rem = idx - l * 6144;
        int n = rem / 96;
        int g = rem - n * 96;
        int c = g >> 4, local = g & 15;
        int ks = local >> 3, lmod = local & 7;
        int half = lmod >> 2, lm = lmod & 3;
        int P = ks * 4 + lm;
        int word = (((l * 64 + n) * 6 + c) * 8 + P) * 2 + half;
        float v[2];
#pragma unroll
        for (int u = 0; u < 2; u++) {
            int k = g * 2 + u;
            if (l == 0) {
                int hop = k >> 6, cc = k & 63;
                v[u] = (cc < IN_F) ? W0[(hop * IN_F + cc) * 64 + n] : 0.0f;
            } else if (l == 1) v[u] = W1[k * 64 + n];
            else if (l == 2)   v[u] = W2[k * 64 + n];
            else               v[u] = W3[k * 64 + n];
        }
        uint32_t hw = pack_bf16x2(v[0], v[1]);
        float v0h = __uint_as_float(hw << 16);
        float v1h = __uint_as_float(hw & 0xffff0000u);
        uint32_t lw = pack_bf16x2(v[0] - v0h, v[1] - v1h);
        g_Wbh[word] = hw;
        g_Wbl[word] = lw;
    }
}

// ---------------- scan ----------------
__global__ void k_scan1() {
    __shared__ int sh[SCAN_BS];
    int i = blockIdx.x * SCAN_BS + threadIdx.x;
    int v = (i < NN) ? g_deg[i] : 0;
    sh[threadIdx.x] = v;
    __syncthreads();
    for (int off = 1; off < SCAN_BS; off <<= 1) {
        int t = (threadIdx.x >= off) ? sh[threadIdx.x - off] : 0;
        __syncthreads();
        sh[threadIdx.x] += t;
        __syncthreads();
    }
    if (i < NN) g_incl[i] = sh[threadIdx.x];
    if (threadIdx.x == SCAN_BS - 1) g_bsums[blockIdx.x] = sh[threadIdx.x];
}
__global__ void k_scan2() {
    __shared__ int sh[1024];
    int t = threadIdx.x;
    int orig = (t < SCAN_NB) ? g_bsums[t] : 0;
    sh[t] = orig;
    __syncthreads();
    for (int off = 1; off < 1024; off <<= 1) {
        int v = (t >= off) ? sh[t - off] : 0;
        __syncthreads();
        sh[t] += v;
        __syncthreads();
    }
    if (t < SCAN_NB) g_bsums[t] = sh[t] - orig;
}
__global__ void k_scan3() {   // rowptr/cursor/norm; zeroes g_deg for next replay
    int i = blockIdx.x * blockDim.x + threadIdx.x;
    if (i < NN) {
        int d = g_deg[i];
        int ex = g_incl[i] - d + g_bsums[i / SCAN_BS];
        g_rowptr[i] = ex;
        g_cursor[i] = ex;
        g_norm[i] = rsqrtf(fmaxf((float)d, 1.0f));
        g_deg[i] = 0;
    }
    if (i == 0) g_rowptr[NN] = EE;
}
__global__ void k_fill(const int* __restrict__ src, const int* __restrict__ dst) {
    int i = blockIdx.x * blockDim.x + threadIdx.x;
    if (i < EE) {
        int p = atomicAdd(&g_cursor[dst[i]], 1);
        g_col[p] = src[i];
    }
}

// ---------------- SpMM hop on packed buffers ----------------
// C4 = float4-groups of columns (16 = 64 cols, 8 = lower 32 cols)
template <int C4>
__global__ void __launch_bounds__(256) k_spmm(const uint32_t* __restrict__ Hin,
                                              uint32_t* __restrict__ Hout) {
    constexpr int EP = 32 / C4;
    int node = blockIdx.x * 8 + (threadIdx.x >> 5);
    if (node >= NN) return;
    int lane = threadIdx.x & 31;
    int grp = lane / C4;
    int q = lane % C4;
    int s = g_rowptr[node], e = g_rowptr[node + 1];
    float4 acc = make_float4(0.f, 0.f, 0.f, 0.f);

    int j = s + grp;
    for (; j + EP < e; j += 2 * EP) {
        int u0 = __ldg(&g_col[j]);
        int u1 = __ldg(&g_col[j + EP]);
        float n0 = __ldg(&g_norm[u0]);
        float n1 = __ldg(&g_norm[u1]);
        uint4 p0 = *(const uint4*)&Hin[(size_t)u0 * 64 + q * 4];
        uint4 p1 = *(const uint4*)&Hin[(size_t)u1 * 64 + q * 4];
        acc.x += n0 * recon(p0.x); acc.y += n0 * recon(p0.y);
        acc.z += n0 * recon(p0.z); acc.w += n0 * recon(p0.w);
        acc.x += n1 * recon(p1.x); acc.y += n1 * recon(p1.y);
        acc.z += n1 * recon(p1.z); acc.w += n1 * recon(p1.w);
    }
    if (j < e) {
        int u = __ldg(&g_col[j]);
        float nu = __ldg(&g_norm[u]);
        uint4 p = *(const uint4*)&Hin[(size_t)u * 64 + q * 4];
        acc.x += nu * recon(p.x); acc.y += nu * recon(p.y);
        acc.z += nu * recon(p.z); acc.w += nu * recon(p.w);
    }
#pragma unroll
    for (int off = 16; off >= C4; off >>= 1) {
        acc.x += __shfl_xor_sync(0xffffffffu, acc.x, off);
        acc.y += __shfl_xor_sync(0xffffffffu, acc.y, off);
        acc.z += __shfl_xor_sync(0xffffffffu, acc.z, off);
        acc.w += __shfl_xor_sync(0xffffffffu, acc.w, off);
    }
    if (lane < C4) {
        float nv = g_norm[node];
        uint4 o;
        o.x = packf(nv * acc.x);
        o.y = packf(nv * acc.y);
        o.z = packf(nv * acc.z);
        o.w = packf(nv * acc.w);
        *(uint4*)&Hout[(size_t)node * 64 + q * 4] = o;
        if (C4 == 8)
            *(uint4*)&Hout[(size_t)node * 64 + 32 + q * 4] = make_uint4(0u, 0u, 0u, 0u);
    }
}

// ---------------- bf16-split tensor-core GEMM + bias + ReLU ----------------
#define ASTR 20
#define BPSTR 12   // uint2 stride per n-column

__device__ __forceinline__ void mma_bf16(float* c, uint32_t a0, uint32_t a1,
                                         uint32_t a2, uint32_t a3,
                                         uint32_t b0, uint32_t b1) {
    asm volatile(
        "mma.sync.aligned.m16n8k16.row.col.f32.bf16.bf16.f32 "
        "{%0,%1,%2,%3}, {%4,%5,%6,%7}, {%8,%9}, {%0,%1,%2,%3};"
        : "+f"(c[0]), "+f"(c[1]), "+f"(c[2]), "+f"(c[3])
        : "r"(a0), "r"(a1), "r"(a2), "r"(a3), "r"(b0), "r"(b1));
}

__global__ void __launch_bounds__(256) k_gemm_tc(
    const uint32_t* __restrict__ H0, const uint32_t* __restrict__ H1,
    const uint32_t* __restrict__ H2, const uint32_t* __restrict__ Wbh,
    const uint32_t* __restrict__ Wbl, const float* __restrict__ bias,
    uint32_t* __restrict__ Out)
{
    __shared__ float sbias[64];
    __shared__ uint32_t Ahi[128 * ASTR];
    __shared__ uint32_t Alo[128 * ASTR];
    __shared__ uint2 Bhi2[64 * BPSTR];
    __shared__ uint2 Blo2[64 * BPSTR];

    int tid = threadIdx.x;
    int warp = tid >> 5, lane = tid & 31;
    int lg = lane >> 2, lm = lane & 3;
    int row0 = blockIdx.x * 128;
    if (tid < 64) sbias[tid] = bias[tid];

    float acc[8][4];
#pragma unroll
    for (int nt = 0; nt < 8; nt++)
#pragma unroll
        for (int jj = 0; jj < 4; jj++) acc[nt][jj] = 0.f;

    const uint32_t* bufs[3] = {H0, H1, H2};
    const uint2* Wh2 = (const uint2*)Wbh;
    const uint2* Wl2 = (const uint2*)Wbl;

    for (int c = 0; c < 6; c++) {
        __syncthreads();
        // ---- stage A (128 rows x 32 k), PRMT split of packed words ----
        {
            const uint32_t* H = bufs[c >> 1];
            int half = (c & 1) * 32;
#pragma unroll
            for (int it = 0; it < 4; it++) {
                int idx = tid + it * 256;          // 0..1023 uint4s
                int r = idx >> 3, q = idx & 7;
                uint4 w = *(const uint4*)&H[(size_t)(row0 + r) * 64 + half + q * 4];
                uint32_t h0 = __byte_perm(w.x, w.y, 0x5410);
                uint32_t h1 = __byte_perm(w.z, w.w, 0x5410);
                uint32_t l0 = __byte_perm(w.x, w.y, 0x7632);
                uint32_t l1 = __byte_perm(w.z, w.w, 0x7632);
                int off = r * ASTR + q * 2;
                *(uint2*)&Ahi[off] = make_uint2(h0, h1);
                *(uint2*)&Alo[off] = make_uint2(l0, l1);
            }
        }
        // ---- stage B (64 n x 8 pairs) ----
        {
#pragma unroll
            for (int it = 0; it < 2; it++) {
                int idx = tid + it * 256;          // 0..511
                int n = idx >> 3, P = idx & 7;
                int srcp = (n * 6 + c) * 8 + P;
                Bhi2[n * BPSTR + P] = Wh2[srcp];
                Blo2[n * BPSTR + P] = Wl2[srcp];
            }
        }
        __syncthreads();

        int rA = warp * 16 + lg;
#pragma unroll
        for (int ks = 0; ks < 2; ks++) {
            int kb = ks * 8 + lm;
            uint32_t ah0 = Ahi[rA * ASTR + kb];
            uint32_t ah1 = Ahi[(rA + 8) * ASTR + kb];
            uint32_t ah2 = Ahi[rA * ASTR + kb + 4];
            uint32_t ah3 = Ahi[(rA + 8) * ASTR + kb + 4];
            uint32_t al0 = Alo[rA * ASTR + kb];
            uint32_t al1 = Alo[(rA + 8) * ASTR + kb];
            uint32_t al2 = Alo[rA * ASTR + kb + 4];
            uint32_t al3 = Alo[(rA + 8) * ASTR + kb + 4];
            int bp = ks * 4 + lm;
#pragma unroll
            for (int nt = 0; nt < 8; nt++) {
                int col = nt * 8 + lg;
                uint2 bh = Bhi2[col * BPSTR + bp];
                uint2 bl = Blo2[col * BPSTR + bp];
                mma_bf16(acc[nt], ah0, ah1, ah2, ah3, bh.x, bh.y);
                mma_bf16(acc[nt], al0, al1, al2, al3, bh.x, bh.y);
                mma_bf16(acc[nt], ah0, ah1, ah2, ah3, bl.x, bl.y);
            }
        }
    }

    // ---- epilogue: bias + relu + pack + store ----
    int r = row0 + warp * 16 + lg;
    int cb = lm * 2;
#pragma unroll
    for (int nt = 0; nt < 8; nt++) {
        int col = nt * 8 + cb;
        float b0 = sbias[col], b1 = sbias[col + 1];
        uint2 o0, o1;
        o0.x = packf(fmaxf(acc[nt][0] + b0, 0.f));
        o0.y = packf(fmaxf(acc[nt][1] + b1, 0.f));
        o1.x = packf(fmaxf(acc[nt][2] + b0, 0.f));
        o1.y = packf(fmaxf(acc[nt][3] + b1, 0.f));
        *(uint2*)&Out[(size_t)r * 64 + col] = o0;
        *(uint2*)&Out[(size_t)(r + 8) * 64 + col] = o1;
    }
}

// ---------------- per-graph attention pooling (packed input) ----------------
__global__ void k_pool(const uint32_t* __restrict__ H, const float* __restrict__ Wg,
                       const float* __restrict__ bg, float* __restrict__ out) {
    int g = blockIdx.x;
    __shared__ float sWg[64];
    __shared__ float sgate[NPG];
    __shared__ float red[256];
    int t = threadIdx.x;
    if (t < 64) sWg[t] = Wg[t];
    __syncthreads();

    int lane = t & 31, w = t >> 5;
    float bgv = bg[0];
    for (int n = w; n < NPG; n += 8) {
        const uint32_t* hp = H + (size_t)(g * NPG + n) * LD;
        float v = recon(hp[lane]) * sWg[lane] + recon(hp[lane + 32]) * sWg[lane + 32];
#pragma unroll
        for (int o = 16; o; o >>= 1) v += __shfl_xor_sync(0xffffffffu, v, o);
        if (lane == 0) sgate[n] = v + bgv;
    }
    __syncthreads();

    float m = -INFINITY;
    for (int n = t; n < NPG; n += 256) m = fmaxf(m, sgate[n]);
    red[t] = m;
    __syncthreads();
    for (int s = 128; s; s >>= 1) { if (t < s) red[t] = fmaxf(red[t], red[t + s]); __syncthreads(); }
    float gmax = red[0];
    __syncthreads();

    float ssum = 0.f;
    for (int n = t; n < NPG; n += 256) {
        float e = expf(sgate[n] - gmax);
        sgate[n] = e;
        ssum += e;
    }
    red[t] = ssum;
    __syncthreads();
    for (int s = 128; s; s >>= 1) { if (t < s) red[t] += red[t + s]; __syncthreads(); }
    float z = red[0];
    __syncthreads();

    int d = t & 63, p = t >> 6;
    float acc = 0.f;
    for (int n = p; n < NPG; n += 4)
        acc += sgate[n] * recon(H[(size_t)(g * NPG + n) * LD + d]);
    red[t] = acc;
    __syncthreads();
    if (t < 64)
        out[g * 64 + t] = (red[t] + red[t + 64] + red[t + 128] + red[t + 192]) / z;
}

// ---------------- launch ----------------
extern "C" void kernel_launch(void* const* d_in, const int* in_sizes, int n_in,
                              void* d_out, int out_size) {
    const float* x   = (const float*)d_in[0];
    const int*   src = (const int*)d_in[1];
    const int*   dst = (const int*)d_in[2];
    const float* W0 = (const float*)d_in[4];
    const float* b0 = (const float*)d_in[5];
    const float* W1 = (const float*)d_in[6];
    const float* b1 = (const float*)d_in[7];
    const float* W2 = (const float*)d_in[8];
    const float* b2 = (const float*)d_in[9];
    const float* W3 = (const float*)d_in[10];
    const float* b3 = (const float*)d_in[11];
    const float* Wg = (const float*)d_in[12];
    const float* bg = (const float*)d_in[13];
    float* out = (float*)d_out;

    uint32_t *M0, *M1, *T1, *T2, *Wbh, *Wbl;
    cudaGetSymbolAddress((void**)&M0, g_M0);
    cudaGetSymbolAddress((void**)&M1, g_M1);
    cudaGetSymbolAddress((void**)&T1, g_T1);
    cudaGetSymbolAddress((void**)&T2, g_T2);
    cudaGetSymbolAddress((void**)&Wbh, g_Wbh);
    cudaGetSymbolAddress((void**)&Wbl, g_Wbl);

    // launch #0: fused deg-count + pad/pack + weight prep
    k_fused<<<DEG_NB + PAD_NB + WPREP_NB, 256>>>(dst, x, W0, W1, W2, W3);
    k_scan1<<<SCAN_NB, SCAN_BS>>>();          // #1
    k_scan2<<<1, 1024>>>();                   // #2
    k_scan3<<<(NN + 255) / 256, 256>>>();     // #3 (+norm, +deg reset)
    k_fill<<<(EE + 255) / 256, 256>>>(src, dst);  // #4

    const int sgrid = NN / 8;     // 20000
    const int ggrid = NN / 128;   // 1250

    // ---- layer 0 ----  (launch #5 = k_spmm<8> — profiled)
    k_spmm<8><<<sgrid, 256>>>(M0, T1);
    k_spmm<8><<<sgrid, 256>>>(T1, T2);
    k_gemm_tc<<<ggrid, 256>>>(M0, T1, T2, Wbh + 0 * 6144, Wbl + 0 * 6144, b0, M1);

    // ---- layer 1 ----
    k_spmm<16><<<sgrid, 256>>>(M1, T1);
    k_spmm<16><<<sgrid, 256>>>(T1, T2);
    k_gemm_tc<<<ggrid, 256>>>(M1, T1, T2, Wbh + 1 * 6144, Wbl + 1 * 6144, b1, M0);

    // ---- layer 2 ----
    k_spmm<16><<<sgrid, 256>>>(M0, T1);
    k_spmm<16><<<sgrid, 256>>>(T1, T2);
    k_gemm_tc<<<ggrid, 256>>>(M0, T1, T2, Wbh + 2 * 6144, Wbl + 2 * 6144, b2, M1);

    // ---- layer 3 ----
    k_spmm<16><<<sgrid, 256>>>(M1, T1);
    k_spmm<16><<<sgrid, 256>>>(T1, T2);
    k_gemm_tc<<<ggrid, 256>>>(M1, T1, T2, Wbh + 3 * 6144, Wbl + 3 * 6144, b3, M0);

    // ---- pooling ----
    k_pool<<<GG, 256>>>(M0, Wg, bg, out);
}

// round 6
// speedup vs baseline: 1.7851x; 1.2347x over previous
#include <cuda_runtime.h>
#include <cuda_bf16.h>
#include <math.h>
#include <stdint.h>

#define NN 160000
#define GG 800
#define NPG 200
#define EE 1280000
#define IN_F 31
#define HID 64
#define LD 64

// ---------------- static device scratch ----------------
__device__ int   g_deg[NN];
__device__ float g_norm[NN];
__device__ int2  g_row[NN];       // {start, end}
__device__ int   g_cursor[NN];
__device__ int   g_col[EE];
__device__ int   g_ctr;

// bf16 feature planes [N][64]
__device__ uint16_t g_M0 [NN * LD];   // padded x
__device__ uint16_t g_M0s[NN * LD];   // norm * x
__device__ uint16_t g_P0 [NN * LD];   // layer outputs ping
__device__ uint16_t g_P0s[NN * LD];
__device__ uint16_t g_P1 [NN * LD];   // layer outputs pong
__device__ uint16_t g_P1s[NN * LD];
__device__ uint16_t g_T1 [NN * LD];   // hop1
__device__ uint16_t g_T1s[NN * LD];
__device__ uint16_t g_T2 [NN * LD];   // hop2

// weights bf16 hi/lo, pair-interleaved: word idx = (((l*64+n)*6+c)*8+P)*2+half
__device__ uint32_t g_Wbh[4 * 64 * 96];
__device__ uint32_t g_Wbl[4 * 64 * 96];

// pack (x -> low half, y -> high half) as bf16x2
__device__ __forceinline__ uint32_t pack_bf16x2(float x, float y) {
    uint32_t r;
    asm("cvt.rn.bf16x2.f32 %0, %1, %2;" : "=r"(r) : "f"(y), "f"(x));
    return r;
}
__device__ __forceinline__ uint16_t f2b(float v) {
    return (uint16_t)(pack_bf16x2(v, 0.0f) & 0xffffu);
}
__device__ __forceinline__ float blo(uint32_t w) { return __uint_as_float(w << 16); }
__device__ __forceinline__ float bhi(uint32_t w) { return __uint_as_float(w & 0xffff0000u); }
__device__ __forceinline__ float b2f(uint16_t h) { return __uint_as_float(((uint32_t)h) << 16); }

// ---------------- launch 0: degree count + weight prep + ctr reset ----------------
#define DEG_NB 5000
#define WPREP_NB 96

__global__ void k_fused(const int* __restrict__ dst,
                        const float* __restrict__ W0, const float* __restrict__ W1,
                        const float* __restrict__ W2, const float* __restrict__ W3) {
    int b = blockIdx.x, t = threadIdx.x;
    if (b == 0 && t == 0) g_ctr = 0;
    if (b < DEG_NB) {
        int i = b * 256 + t;
        if (i < EE) atomicAdd(&g_deg[dst[i]], 1);
    } else {
        int idx = (b - DEG_NB) * 256 + t;  // < 4*64*96
        int l = idx / 6144;
        int rem = idx - l * 6144;
        int n = rem / 96;
        int g = rem - n * 96;
        int c = g >> 4, local = g & 15;
        int ks = local >> 3, lmod = local & 7;
        int half = lmod >> 2, lm = lmod & 3;
        int P = ks * 4 + lm;
        int word = (((l * 64 + n) * 6 + c) * 8 + P) * 2 + half;
        float v[2];
#pragma unroll
        for (int u = 0; u < 2; u++) {
            int k = g * 2 + u;
            if (l == 0) {
                int hop = k >> 6, cc = k & 63;
                v[u] = (cc < IN_F) ? W0[(hop * IN_F + cc) * 64 + n] : 0.0f;
            } else if (l == 1) v[u] = W1[k * 64 + n];
            else if (l == 2)   v[u] = W2[k * 64 + n];
            else               v[u] = W3[k * 64 + n];
        }
        uint32_t hw = pack_bf16x2(v[0], v[1]);
        float v0h = blo(hw);
        float v1h = bhi(hw);
        uint32_t lw = pack_bf16x2(v[0] - v0h, v[1] - v1h);
        g_Wbh[word] = hw;
        g_Wbl[word] = lw;
    }
}

// ---------------- launch 1: per-node segment base via warp-agg atomic ----------------
__global__ void k_base() {
    int i = blockIdx.x * blockDim.x + threadIdx.x;
    int lane = threadIdx.x & 31;
    int d = (i < NN) ? g_deg[i] : 0;
    int sc = d;
#pragma unroll
    for (int off = 1; off < 32; off <<= 1) {
        int t = __shfl_up_sync(0xffffffffu, sc, off);
        if (lane >= off) sc += t;
    }
    int total = __shfl_sync(0xffffffffu, sc, 31);
    int base = 0;
    if (lane == 31 && total > 0) base = atomicAdd(&g_ctr, total);
    base = __shfl_sync(0xffffffffu, base, 31);
    if (i < NN) {
        int start = base + sc - d;
        g_row[i] = make_int2(start, start + d);
        g_cursor[i] = start;
        g_norm[i] = rsqrtf(fmaxf((float)d, 1.0f));
        g_deg[i] = 0;   // ready for next replay
    }
}

// ---------------- launch 2: edge fill + x pad/pack (needs norm) ----------------
#define FILL_NB 5000
#define PAD_NB 40000

__global__ void k_fillpad(const int* __restrict__ src, const int* __restrict__ dst,
                          const float* __restrict__ x) {
    int b = blockIdx.x, t = threadIdx.x;
    if (b < FILL_NB) {
        int i = b * 256 + t;
        if (i < EE) {
            int p = atomicAdd(&g_cursor[dst[i]], 1);
            g_col[p] = src[i];
        }
    } else {
        int idx = (b - FILL_NB) * 256 + t;   // < NN*64
        int node = idx >> 6, c = idx & 63;
        float v = (c < IN_F) ? x[node * IN_F + c] : 0.0f;
        g_M0[idx] = f2b(v);
        g_M0s[idx] = f2b(v * g_norm[node]);
    }
}

// ---------------- SpMM hop on bf16 planes ----------------
// Gin is pre-scaled (norm[u]*h[u]); out = norm[v] * sum. COLS=32 or 64.
// WS: also write the norm-scaled plane for the next hop.
template <int COLS, bool WS>
__global__ void __launch_bounds__(256) k_spmm(const uint16_t* __restrict__ Gin,
                                              uint16_t* __restrict__ Hout,
                                              uint16_t* __restrict__ Hsout) {
    constexpr int GQ = COLS / 8;    // 8 or 4 column groups (8 bf16 each)
    constexpr int EP = 32 / GQ;     // 4 or 8 edges in parallel
    int node = blockIdx.x * 8 + (threadIdx.x >> 5);
    if (node >= NN) return;
    int lane = threadIdx.x & 31;
    int q = lane & (GQ - 1);
    int grp = lane / GQ;
    int2 se = g_row[node];
    float a0 = 0.f, a1 = 0.f, a2 = 0.f, a3 = 0.f;
    float a4 = 0.f, a5 = 0.f, a6 = 0.f, a7 = 0.f;

    int j = se.x + grp;
    for (; j + EP < se.y; j += 2 * EP) {
        int u0 = __ldg(&g_col[j]);
        int u1 = __ldg(&g_col[j + EP]);
        uint4 p0 = *(const uint4*)&Gin[(size_t)u0 * 64 + q * 8];
        uint4 p1 = *(const uint4*)&Gin[(size_t)u1 * 64 + q * 8];
        a0 += blo(p0.x); a1 += bhi(p0.x); a2 += blo(p0.y); a3 += bhi(p0.y);
        a4 += blo(p0.z); a5 += bhi(p0.z); a6 += blo(p0.w); a7 += bhi(p0.w);
        a0 += blo(p1.x); a1 += bhi(p1.x); a2 += blo(p1.y); a3 += bhi(p1.y);
        a4 += blo(p1.z); a5 += bhi(p1.z); a6 += blo(p1.w); a7 += bhi(p1.w);
    }
    if (j < se.y) {
        int u = __ldg(&g_col[j]);
        uint4 p = *(const uint4*)&Gin[(size_t)u * 64 + q * 8];
        a0 += blo(p.x); a1 += bhi(p.x); a2 += blo(p.y); a3 += bhi(p.y);
        a4 += blo(p.z); a5 += bhi(p.z); a6 += blo(p.w); a7 += bhi(p.w);
    }
#pragma unroll
    for (int off = 16; off >= GQ; off >>= 1) {
        a0 += __shfl_xor_sync(0xffffffffu, a0, off);
        a1 += __shfl_xor_sync(0xffffffffu, a1, off);
        a2 += __shfl_xor_sync(0xffffffffu, a2, off);
        a3 += __shfl_xor_sync(0xffffffffu, a3, off);
        a4 += __shfl_xor_sync(0xffffffffu, a4, off);
        a5 += __shfl_xor_sync(0xffffffffu, a5, off);
        a6 += __shfl_xor_sync(0xffffffffu, a6, off);
        a7 += __shfl_xor_sync(0xffffffffu, a7, off);
    }
    if (lane < GQ) {
        float nv = g_norm[node];
        float o0 = nv * a0, o1 = nv * a1, o2 = nv * a2, o3 = nv * a3;
        float o4 = nv * a4, o5 = nv * a5, o6 = nv * a6, o7 = nv * a7;
        uint4 w;
        w.x = pack_bf16x2(o0, o1); w.y = pack_bf16x2(o2, o3);
        w.z = pack_bf16x2(o4, o5); w.w = pack_bf16x2(o6, o7);
        *(uint4*)&Hout[(size_t)node * 64 + q * 8] = w;
        if (WS) {
            uint4 ws;
            ws.x = pack_bf16x2(nv * o0, nv * o1); ws.y = pack_bf16x2(nv * o2, nv * o3);
            ws.z = pack_bf16x2(nv * o4, nv * o5); ws.w = pack_bf16x2(nv * o6, nv * o7);
            *(uint4*)&Hsout[(size_t)node * 64 + q * 8] = ws;
        }
    } else if (COLS == 32 && lane < 2 * GQ) {
        // zero the upper 32 columns (stale from previous replay)
        uint4 z = make_uint4(0u, 0u, 0u, 0u);
        *(uint4*)&Hout[(size_t)node * 64 + 32 + (lane - GQ) * 8] = z;
        if (WS) *(uint4*)&Hsout[(size_t)node * 64 + 32 + (lane - GQ) * 8] = z;
    }
}

// ---------------- bf16 tensor-core GEMM + bias + ReLU ----------------
// Out[128,64] = relu( concat(H0,H1,H2)[128,192] @ W[192,64] + bias )
// A pure bf16; W split hi/lo -> 2 mma per fragment.
#define ASTR 20
#define BPSTR 12

__device__ __forceinline__ void mma_bf16(float* c, uint32_t a0, uint32_t a1,
                                         uint32_t a2, uint32_t a3,
                                         uint32_t b0, uint32_t b1) {
    asm volatile(
        "mma.sync.aligned.m16n8k16.row.col.f32.bf16.bf16.f32 "
        "{%0,%1,%2,%3}, {%4,%5,%6,%7}, {%8,%9}, {%0,%1,%2,%3};"
        : "+f"(c[0]), "+f"(c[1]), "+f"(c[2]), "+f"(c[3])
        : "r"(a0), "r"(a1), "r"(a2), "r"(a3), "r"(b0), "r"(b1));
}

// WSC: write scaled plane for next layer's hop1
template <bool WSC>
__global__ void __launch_bounds__(256) k_gemm_tc(
    const uint16_t* __restrict__ H0, const uint16_t* __restrict__ H1,
    const uint16_t* __restrict__ H2, const uint32_t* __restrict__ Wbh,
    const uint32_t* __restrict__ Wbl, const float* __restrict__ bias,
    uint16_t* __restrict__ Out, uint16_t* __restrict__ OutS)
{
    __shared__ float sbias[64];
    __shared__ uint32_t As[128 * ASTR];
    __shared__ uint2 Bhi2[64 * BPSTR];
    __shared__ uint2 Blo2[64 * BPSTR];

    int tid = threadIdx.x;
    int warp = tid >> 5, lane = tid & 31;
    int lg = lane >> 2, lm = lane & 3;
    int row0 = blockIdx.x * 128;
    if (tid < 64) sbias[tid] = bias[tid];

    float acc[8][4];
#pragma unroll
    for (int nt = 0; nt < 8; nt++)
#pragma unroll
        for (int jj = 0; jj < 4; jj++) acc[nt][jj] = 0.f;

    const uint16_t* bufs[3] = {H0, H1, H2};
    const uint2* Wh2 = (const uint2*)Wbh;
    const uint2* Wl2 = (const uint2*)Wbl;

    for (int c = 0; c < 6; c++) {
        __syncthreads();
        // ---- stage A (128 rows x 32 k bf16): direct copy ----
        {
            const uint16_t* H = bufs[c >> 1];
            int half = (c & 1) * 32;
#pragma unroll
            for (int it = 0; it < 2; it++) {
                int idx = tid + it * 256;          // 0..511
                int r = idx >> 2, q = idx & 3;
                uint4 w = *(const uint4*)&H[(size_t)(row0 + r) * 64 + half + q * 8];
                *(uint4*)&As[r * ASTR + q * 4] = w;
            }
        }
        // ---- stage B (64 n x 8 pairs) ----
        {
#pragma unroll
            for (int it = 0; it < 2; it++) {
                int idx = tid + it * 256;          // 0..511
                int n = idx >> 3, P = idx & 7;
                int srcp = (n * 6 + c) * 8 + P;
                Bhi2[n * BPSTR + P] = Wh2[srcp];
                Blo2[n * BPSTR + P] = Wl2[srcp];
            }
        }
        __syncthreads();

        int rA = warp * 16 + lg;
#pragma unroll
        for (int ks = 0; ks < 2; ks++) {
            int kb = ks * 8 + lm;
            uint32_t a0 = As[rA * ASTR + kb];
            uint32_t a1 = As[(rA + 8) * ASTR + kb];
            uint32_t a2 = As[rA * ASTR + kb + 4];
            uint32_t a3 = As[(rA + 8) * ASTR + kb + 4];
            int bp = ks * 4 + lm;
#pragma unroll
            for (int nt = 0; nt < 8; nt++) {
                int col = nt * 8 + lg;
                uint2 bh = Bhi2[col * BPSTR + bp];
                uint2 bl = Blo2[col * BPSTR + bp];
                mma_bf16(acc[nt], a0, a1, a2, a3, bh.x, bh.y);
                mma_bf16(acc[nt], a0, a1, a2, a3, bl.x, bl.y);
            }
        }
    }

    // ---- epilogue: bias + relu + bf16 store (+ scaled plane) ----
    int r = row0 + warp * 16 + lg;
    float nv0 = 1.f, nv1 = 1.f;
    if (WSC) { nv0 = g_norm[r]; nv1 = g_norm[r + 8]; }
    int cb = lm * 2;
#pragma unroll
    for (int nt = 0; nt < 8; nt++) {
        int col = nt * 8 + cb;
        float b0 = sbias[col], b1 = sbias[col + 1];
        float v00 = fmaxf(acc[nt][0] + b0, 0.f);
        float v01 = fmaxf(acc[nt][1] + b1, 0.f);
        float v10 = fmaxf(acc[nt][2] + b0, 0.f);
        float v11 = fmaxf(acc[nt][3] + b1, 0.f);
        *(uint32_t*)&Out[(size_t)r * 64 + col] = pack_bf16x2(v00, v01);
        *(uint32_t*)&Out[(size_t)(r + 8) * 64 + col] = pack_bf16x2(v10, v11);
        if (WSC) {
            *(uint32_t*)&OutS[(size_t)r * 64 + col] = pack_bf16x2(nv0 * v00, nv0 * v01);
            *(uint32_t*)&OutS[(size_t)(r + 8) * 64 + col] = pack_bf16x2(nv1 * v10, nv1 * v11);
        }
    }
}

// ---------------- per-graph attention pooling (bf16 plane input) ----------------
__global__ void k_pool(const uint16_t* __restrict__ H, const float* __restrict__ Wg,
                       const float* __restrict__ bg, float* __restrict__ out) {
    int g = blockIdx.x;
    __shared__ float sWg[64];
    __shared__ float sgate[NPG];
    __shared__ float red[256];
    int t = threadIdx.x;
    if (t < 64) sWg[t] = Wg[t];
    __syncthreads();

    int lane = t & 31, w = t >> 5;
    float bgv = bg[0];
    for (int n = w; n < NPG; n += 8) {
        const uint16_t* hp = H + (size_t)(g * NPG + n) * LD;
        float v = b2f(hp[lane]) * sWg[lane] + b2f(hp[lane + 32]) * sWg[lane + 32];
#pragma unroll
        for (int o = 16; o; o >>= 1) v += __shfl_xor_sync(0xffffffffu, v, o);
        if (lane == 0) sgate[n] = v + bgv;
    }
    __syncthreads();

    float m = -INFINITY;
    for (int n = t; n < NPG; n += 256) m = fmaxf(m, sgate[n]);
    red[t] = m;
    __syncthreads();
    for (int s = 128; s; s >>= 1) { if (t < s) red[t] = fmaxf(red[t], red[t + s]); __syncthreads(); }
    float gmax = red[0];
    __syncthreads();

    float ssum = 0.f;
    for (int n = t; n < NPG; n += 256) {
        float e = expf(sgate[n] - gmax);
        sgate[n] = e;
        ssum += e;
    }
    red[t] = ssum;
    __syncthreads();
    for (int s = 128; s; s >>= 1) { if (t < s) red[t] += red[t + s]; __syncthreads(); }
    float z = red[0];
    __syncthreads();

    int d = t & 63, p = t >> 6;
    float acc = 0.f;
    for (int n = p; n < NPG; n += 4)
        acc += sgate[n] * b2f(H[(size_t)(g * NPG + n) * LD + d]);
    red[t] = acc;
    __syncthreads();
    if (t < 64)
        out[g * 64 + t] = (red[t] + red[t + 64] + red[t + 128] + red[t + 192]) / z;
}

// ---------------- launch ----------------
extern "C" void kernel_launch(void* const* d_in, const int* in_sizes, int n_in,
                              void* d_out, int out_size) {
    const float* x   = (const float*)d_in[0];
    const int*   src = (const int*)d_in[1];
    const int*   dst = (const int*)d_in[2];
    const float* W0 = (const float*)d_in[4];
    const float* b0 = (const float*)d_in[5];
    const float* W1 = (const float*)d_in[6];
    const float* b1 = (const float*)d_in[7];
    const float* W2 = (const float*)d_in[8];
    const float* b2 = (const float*)d_in[9];
    const float* W3 = (const float*)d_in[10];
    const float* b3 = (const float*)d_in[11];
    const float* Wg = (const float*)d_in[12];
    const float* bg = (const float*)d_in[13];
    float* out = (float*)d_out;

    uint16_t *M0, *M0s, *P0, *P0s, *P1, *P1s, *T1, *T1s, *T2;
    uint32_t *Wbh, *Wbl;
    cudaGetSymbolAddress((void**)&M0, g_M0);
    cudaGetSymbolAddress((void**)&M0s, g_M0s);
    cudaGetSymbolAddress((void**)&P0, g_P0);
    cudaGetSymbolAddress((void**)&P0s, g_P0s);
    cudaGetSymbolAddress((void**)&P1, g_P1);
    cudaGetSymbolAddress((void**)&P1s, g_P1s);
    cudaGetSymbolAddress((void**)&T1, g_T1);
    cudaGetSymbolAddress((void**)&T1s, g_T1s);
    cudaGetSymbolAddress((void**)&T2, g_T2);
    cudaGetSymbolAddress((void**)&Wbh, g_Wbh);
    cudaGetSymbolAddress((void**)&Wbl, g_Wbl);

    k_fused<<<DEG_NB + WPREP_NB, 256>>>(dst, W0, W1, W2, W3);        // #0
    k_base<<<(NN + 255) / 256, 256>>>();                             // #1
    k_fillpad<<<FILL_NB + PAD_NB, 256>>>(src, dst, x);               // #2

    const int sgrid = NN / 8;     // 20000
    const int ggrid = NN / 128;   // 1250

    // ---- layer 0 ----  (#3 = first spmm — target of ncu capture)
    k_spmm<32, true><<<sgrid, 256>>>(M0s, T1, T1s);
    k_spmm<32, false><<<sgrid, 256>>>(T1s, T2, nullptr);
    k_gemm_tc<true><<<ggrid, 256>>>(M0, T1, T2, Wbh + 0 * 6144, Wbl + 0 * 6144, b0, P0, P0s);

    // ---- layer 1 ----
    k_spmm<64, true><<<sgrid, 256>>>(P0s, T1, T1s);
    k_spmm<64, false><<<sgrid, 256>>>(T1s, T2, nullptr);
    k_gemm_tc<true><<<ggrid, 256>>>(P0, T1, T2, Wbh + 1 * 6144, Wbl + 1 * 6144, b1, P1, P1s);

    // ---- layer 2 ----
    k_spmm<64, true><<<sgrid, 256>>>(P1s, T1, T1s);
    k_spmm<64, false><<<sgrid, 256>>>(T1s, T2, nullptr);
    k_gemm_tc<true><<<ggrid, 256>>>(P1, T1, T2, Wbh + 2 * 6144, Wbl + 2 * 6144, b2, P0, P0s);

    // ---- layer 3 ----
    k_spmm<64, true><<<sgrid, 256>>>(P0s, T1, T1s);
    k_spmm<64, false><<<sgrid, 256>>>(T1s, T2, nullptr);
    k_gemm_tc<false><<<ggrid, 256>>>(P0, T1, T2, Wbh + 3 * 6144, Wbl + 3 * 6144, b3, P1, nullptr);

    // ---- pooling ----
    k_pool<<<GG, 256>>>(P1, Wg, bg, out);
}

// round 7
// speedup vs baseline: 1.9822x; 1.1104x over previous
#include <cuda_runtime.h>
#include <cuda_bf16.h>
#include <math.h>
#include <stdint.h>

#define NN 160000
#define GG 800
#define NPG 200
#define EE 1280000
#define IN_F 31
#define HID 64
#define LD 64

// ---------------- static device scratch ----------------
__device__ int   g_deg[NN];
__device__ float g_norm[NN];
__device__ int2  g_row[NN];       // {start, end}
__device__ int   g_cursor[NN];
__device__ int   g_col[EE];
__device__ int   g_ctr;

// bf16 planes (GEMM inputs / pool input)
__device__ uint16_t g_M0[NN * LD];
__device__ uint16_t g_P0[NN * LD];
__device__ uint16_t g_P1[NN * LD];
__device__ uint16_t g_T1[NN * LD];
__device__ uint16_t g_T2[NN * LD];
// fp32 norm-scaled gather planes (SpMM inputs)
__device__ float g_M0s[NN * LD];
__device__ float g_P0s[NN * LD];
__device__ float g_P1s[NN * LD];
__device__ float g_T1s[NN * LD];

// weights bf16 hi/lo, pair-interleaved: word idx = (((l*64+n)*6+c)*8+P)*2+half
__device__ uint32_t g_Wbh[4 * 64 * 96];
__device__ uint32_t g_Wbl[4 * 64 * 96];

__device__ __forceinline__ uint32_t pack_bf16x2(float x, float y) {
    uint32_t r;
    asm("cvt.rn.bf16x2.f32 %0, %1, %2;" : "=r"(r) : "f"(y), "f"(x));
    return r;
}
__device__ __forceinline__ uint16_t f2b(float v) {
    return (uint16_t)(pack_bf16x2(v, 0.0f) & 0xffffu);
}
__device__ __forceinline__ float blo(uint32_t w) { return __uint_as_float(w << 16); }
__device__ __forceinline__ float bhi(uint32_t w) { return __uint_as_float(w & 0xffff0000u); }
__device__ __forceinline__ float b2f(uint16_t h) { return __uint_as_float(((uint32_t)h) << 16); }

// ---------------- launch 0: degree count + weight prep + ctr reset ----------------
#define DEG_NB 5000
#define WPREP_NB 96

__global__ void k_fused(const int* __restrict__ dst,
                        const float* __restrict__ W0, const float* __restrict__ W1,
                        const float* __restrict__ W2, const float* __restrict__ W3) {
    int b = blockIdx.x, t = threadIdx.x;
    if (b == 0 && t == 0) g_ctr = 0;
    if (b < DEG_NB) {
        int i = b * 256 + t;
        if (i < EE) atomicAdd(&g_deg[dst[i]], 1);
    } else {
        int idx = (b - DEG_NB) * 256 + t;  // < 4*64*96
        int l = idx / 6144;
        int rem = idx - l * 6144;
        int n = rem / 96;
        int g = rem - n * 96;
        int c = g >> 4, local = g & 15;
        int ks = local >> 3, lmod = local & 7;
        int half = lmod >> 2, lm = lmod & 3;
        int P = ks * 4 + lm;
        int word = (((l * 64 + n) * 6 + c) * 8 + P) * 2 + half;
        float v[2];
#pragma unroll
        for (int u = 0; u < 2; u++) {
            int k = g * 2 + u;
            if (l == 0) {
                int hop = k >> 6, cc = k & 63;
                v[u] = (cc < IN_F) ? W0[(hop * IN_F + cc) * 64 + n] : 0.0f;
            } else if (l == 1) v[u] = W1[k * 64 + n];
            else if (l == 2)   v[u] = W2[k * 64 + n];
            else               v[u] = W3[k * 64 + n];
        }
        uint32_t hw = pack_bf16x2(v[0], v[1]);
        uint32_t lw = pack_bf16x2(v[0] - blo(hw), v[1] - bhi(hw));
        g_Wbh[word] = hw;
        g_Wbl[word] = lw;
    }
}

// ---------------- launch 1: per-node segment base via warp-agg atomic ----------------
__global__ void k_base() {
    int i = blockIdx.x * blockDim.x + threadIdx.x;
    int lane = threadIdx.x & 31;
    int d = (i < NN) ? g_deg[i] : 0;
    int sc = d;
#pragma unroll
    for (int off = 1; off < 32; off <<= 1) {
        int t = __shfl_up_sync(0xffffffffu, sc, off);
        if (lane >= off) sc += t;
    }
    int total = __shfl_sync(0xffffffffu, sc, 31);
    int base = 0;
    if (lane == 31 && total > 0) base = atomicAdd(&g_ctr, total);
    base = __shfl_sync(0xffffffffu, base, 31);
    if (i < NN) {
        int start = base + sc - d;
        g_row[i] = make_int2(start, start + d);
        g_cursor[i] = start;
        g_norm[i] = rsqrtf(fmaxf((float)d, 1.0f));
        g_deg[i] = 0;   // ready for next replay
    }
}

// ---------------- launch 2: edge fill + x pad/pack ----------------
#define FILL_NB 5000
#define PAD_NB 40000

__global__ void k_fillpad(const int* __restrict__ src, const int* __restrict__ dst,
                          const float* __restrict__ x) {
    int b = blockIdx.x, t = threadIdx.x;
    if (b < FILL_NB) {
        int i = b * 256 + t;
        if (i < EE) {
            int p = atomicAdd(&g_cursor[dst[i]], 1);
            g_col[p] = src[i];
        }
    } else {
        int idx = (b - FILL_NB) * 256 + t;   // < NN*64
        int node = idx >> 6, c = idx & 63;
        float v = (c < IN_F) ? x[node * IN_F + c] : 0.0f;
        g_M0[idx] = f2b(v);
        g_M0s[idx] = v * g_norm[node];
    }
}

// ---------------- SpMM hop: 8-lane group per node, serial edges, no shuffles ----
// Gin pre-scaled fp32 (norm[u]*h[u]). out_h = norm[v]*sum (bf16); if WS also
// write norm[v]*out_h (fp32) for the next hop. NV = float4s per lane (COLS/32).
template <int NV, bool WS>
__global__ void __launch_bounds__(256) k_spmm(const float* __restrict__ Gin,
                                              uint16_t* __restrict__ Hout,
                                              float* __restrict__ Hsout) {
    int tid = threadIdx.x;
    int node = blockIdx.x * 32 + (tid >> 3);   // grid 5000 * 32 = NN exactly
    int q = tid & 7;
    int2 se = g_row[node];
    const float* gbase = Gin + q * (4 * NV);

    float a0 = 0.f, a1 = 0.f, a2 = 0.f, a3 = 0.f;
    float a4 = 0.f, a5 = 0.f, a6 = 0.f, a7 = 0.f;

    int j = se.x;
    for (; j + 1 < se.y; j += 2) {
        int u0 = __ldg(&g_col[j]);
        int u1 = __ldg(&g_col[j + 1]);
        const float4* r0 = (const float4*)(gbase + (size_t)u0 * 64);
        const float4* r1 = (const float4*)(gbase + (size_t)u1 * 64);
        float4 v00 = r0[0];
        float4 v10 = r1[0];
        a0 += v00.x + v10.x; a1 += v00.y + v10.y;
        a2 += v00.z + v10.z; a3 += v00.w + v10.w;
        if (NV == 2) {
            float4 v01 = r0[1];
            float4 v11 = r1[1];
            a4 += v01.x + v11.x; a5 += v01.y + v11.y;
            a6 += v01.z + v11.z; a7 += v01.w + v11.w;
        }
    }
    if (j < se.y) {
        int u = __ldg(&g_col[j]);
        const float4* r = (const float4*)(gbase + (size_t)u * 64);
        float4 v0 = r[0];
        a0 += v0.x; a1 += v0.y; a2 += v0.z; a3 += v0.w;
        if (NV == 2) {
            float4 v1 = r[1];
            a4 += v1.x; a5 += v1.y; a6 += v1.z; a7 += v1.w;
        }
    }

    float nv = g_norm[node];
    float o0 = nv * a0, o1 = nv * a1, o2 = nv * a2, o3 = nv * a3;
    size_t obase = (size_t)node * 64 + q * (4 * NV);
    if (NV == 1) {
        *(uint2*)&Hout[obase] = make_uint2(pack_bf16x2(o0, o1), pack_bf16x2(o2, o3));
        if (WS)
            *(float4*)&Hsout[obase] = make_float4(nv * o0, nv * o1, nv * o2, nv * o3);
    } else {
        float o4 = nv * a4, o5 = nv * a5, o6 = nv * a6, o7 = nv * a7;
        uint4 w;
        w.x = pack_bf16x2(o0, o1); w.y = pack_bf16x2(o2, o3);
        w.z = pack_bf16x2(o4, o5); w.w = pack_bf16x2(o6, o7);
        *(uint4*)&Hout[obase] = w;
        if (WS) {
            *(float4*)&Hsout[obase] = make_float4(nv * o0, nv * o1, nv * o2, nv * o3);
            *(float4*)&Hsout[obase + 4] = make_float4(nv * o4, nv * o5, nv * o6, nv * o7);
        }
    }
}

// ---------------- bf16 tensor-core GEMM + bias + ReLU ----------------
#define ASTR 20
#define BPSTR 12

__device__ __forceinline__ void mma_bf16(float* c, uint32_t a0, uint32_t a1,
                                         uint32_t a2, uint32_t a3,
                                         uint32_t b0, uint32_t b1) {
    asm volatile(
        "mma.sync.aligned.m16n8k16.row.col.f32.bf16.bf16.f32 "
        "{%0,%1,%2,%3}, {%4,%5,%6,%7}, {%8,%9}, {%0,%1,%2,%3};"
        : "+f"(c[0]), "+f"(c[1]), "+f"(c[2]), "+f"(c[3])
        : "r"(a0), "r"(a1), "r"(a2), "r"(a3), "r"(b0), "r"(b1));
}

template <bool WSC>
__global__ void __launch_bounds__(256) k_gemm_tc(
    const uint16_t* __restrict__ H0, const uint16_t* __restrict__ H1,
    const uint16_t* __restrict__ H2, const uint32_t* __restrict__ Wbh,
    const uint32_t* __restrict__ Wbl, const float* __restrict__ bias,
    uint16_t* __restrict__ Out, float* __restrict__ OutS)
{
    __shared__ float sbias[64];
    __shared__ uint32_t As[128 * ASTR];
    __shared__ uint2 Bhi2[64 * BPSTR];
    __shared__ uint2 Blo2[64 * BPSTR];

    int tid = threadIdx.x;
    int warp = tid >> 5, lane = tid & 31;
    int lg = lane >> 2, lm = lane & 3;
    int row0 = blockIdx.x * 128;
    if (tid < 64) sbias[tid] = bias[tid];

    float acc[8][4];
#pragma unroll
    for (int nt = 0; nt < 8; nt++)
#pragma unroll
        for (int jj = 0; jj < 4; jj++) acc[nt][jj] = 0.f;

    const uint16_t* bufs[3] = {H0, H1, H2};
    const uint2* Wh2 = (const uint2*)Wbh;
    const uint2* Wl2 = (const uint2*)Wbl;

    for (int c = 0; c < 6; c++) {
        __syncthreads();
        {
            const uint16_t* H = bufs[c >> 1];
            int half = (c & 1) * 32;
#pragma unroll
            for (int it = 0; it < 2; it++) {
                int idx = tid + it * 256;
                int r = idx >> 2, q = idx & 3;
                uint4 w = *(const uint4*)&H[(size_t)(row0 + r) * 64 + half + q * 8];
                *(uint4*)&As[r * ASTR + q * 4] = w;
            }
        }
        {
#pragma unroll
            for (int it = 0; it < 2; it++) {
                int idx = tid + it * 256;
                int n = idx >> 3, P = idx & 7;
                int srcp = (n * 6 + c) * 8 + P;
                Bhi2[n * BPSTR + P] = Wh2[srcp];
                Blo2[n * BPSTR + P] = Wl2[srcp];
            }
        }
        __syncthreads();

        int rA = warp * 16 + lg;
#pragma unroll
        for (int ks = 0; ks < 2; ks++) {
            int kb = ks * 8 + lm;
            uint32_t a0 = As[rA * ASTR + kb];
            uint32_t a1 = As[(rA + 8) * ASTR + kb];
            uint32_t a2 = As[rA * ASTR + kb + 4];
            uint32_t a3 = As[(rA + 8) * ASTR + kb + 4];
            int bp = ks * 4 + lm;
#pragma unroll
            for (int nt = 0; nt < 8; nt++) {
                int col = nt * 8 + lg;
                uint2 bh = Bhi2[col * BPSTR + bp];
                uint2 bl = Blo2[col * BPSTR + bp];
                mma_bf16(acc[nt], a0, a1, a2, a3, bh.x, bh.y);
                mma_bf16(acc[nt], a0, a1, a2, a3, bl.x, bl.y);
            }
        }
    }

    int r = row0 + warp * 16 + lg;
    float nv0 = 1.f, nv1 = 1.f;
    if (WSC) { nv0 = g_norm[r]; nv1 = g_norm[r + 8]; }
    int cb = lm * 2;
#pragma unroll
    for (int nt = 0; nt < 8; nt++) {
        int col = nt * 8 + cb;
        float b0 = sbias[col], b1 = sbias[col + 1];
        float v00 = fmaxf(acc[nt][0] + b0, 0.f);
        float v01 = fmaxf(acc[nt][1] + b1, 0.f);
        float v10 = fmaxf(acc[nt][2] + b0, 0.f);
        float v11 = fmaxf(acc[nt][3] + b1, 0.f);
        *(uint32_t*)&Out[(size_t)r * 64 + col] = pack_bf16x2(v00, v01);
        *(uint32_t*)&Out[(size_t)(r + 8) * 64 + col] = pack_bf16x2(v10, v11);
        if (WSC) {
            *(float2*)&OutS[(size_t)r * 64 + col] = make_float2(nv0 * v00, nv0 * v01);
            *(float2*)&OutS[(size_t)(r + 8) * 64 + col] = make_float2(nv1 * v10, nv1 * v11);
        }
    }
}

// ---------------- per-graph attention pooling (bf16 plane input) ----------------
__global__ void k_pool(const uint16_t* __restrict__ H, const float* __restrict__ Wg,
                       const float* __restrict__ bg, float* __restrict__ out) {
    int g = blockIdx.x;
    __shared__ float sWg[64];
    __shared__ float sgate[NPG];
    __shared__ float red[256];
    int t = threadIdx.x;
    if (t < 64) sWg[t] = Wg[t];
    __syncthreads();

    int lane = t & 31, w = t >> 5;
    float bgv = bg[0];
    for (int n = w; n < NPG; n += 8) {
        const uint16_t* hp = H + (size_t)(g * NPG + n) * LD;
        float v = b2f(hp[lane]) * sWg[lane] + b2f(hp[lane + 32]) * sWg[lane + 32];
#pragma unroll
        for (int o = 16; o; o >>= 1) v += __shfl_xor_sync(0xffffffffu, v, o);
        if (lane == 0) sgate[n] = v + bgv;
    }
    __syncthreads();

    float m = -INFINITY;
    for (int n = t; n < NPG; n += 256) m = fmaxf(m, sgate[n]);
    red[t] = m;
    __syncthreads();
    for (int s = 128; s; s >>= 1) { if (t < s) red[t] = fmaxf(red[t], red[t + s]); __syncthreads(); }
    float gmax = red[0];
    __syncthreads();

    float ssum = 0.f;
    for (int n = t; n < NPG; n += 256) {
        float e = expf(sgate[n] - gmax);
        sgate[n] = e;
        ssum += e;
    }
    red[t] = ssum;
    __syncthreads();
    for (int s = 128; s; s >>= 1) { if (t < s) red[t] += red[t + s]; __syncthreads(); }
    float z = red[0];
    __syncthreads();

    int d = t & 63, p = t >> 6;
    float acc = 0.f;
    for (int n = p; n < NPG; n += 4)
        acc += sgate[n] * b2f(H[(size_t)(g * NPG + n) * LD + d]);
    red[t] = acc;
    __syncthreads();
    if (t < 64)
        out[g * 64 + t] = (red[t] + red[t + 64] + red[t + 128] + red[t + 192]) / z;
}

// ---------------- launch ----------------
extern "C" void kernel_launch(void* const* d_in, const int* in_sizes, int n_in,
                              void* d_out, int out_size) {
    const float* x   = (const float*)d_in[0];
    const int*   src = (const int*)d_in[1];
    const int*   dst = (const int*)d_in[2];
    const float* W0 = (const float*)d_in[4];
    const float* b0 = (const float*)d_in[5];
    const float* W1 = (const float*)d_in[6];
    const float* b1 = (const float*)d_in[7];
    const float* W2 = (const float*)d_in[8];
    const float* b2 = (const float*)d_in[9];
    const float* W3 = (const float*)d_in[10];
    const float* b3 = (const float*)d_in[11];
    const float* Wg = (const float*)d_in[12];
    const float* bg = (const float*)d_in[13];
    float* out = (float*)d_out;

    uint16_t *M0, *P0, *P1, *T1, *T2;
    float *M0s, *P0s, *P1s, *T1s;
    uint32_t *Wbh, *Wbl;
    cudaGetSymbolAddress((void**)&M0, g_M0);
    cudaGetSymbolAddress((void**)&P0, g_P0);
    cudaGetSymbolAddress((void**)&P1, g_P1);
    cudaGetSymbolAddress((void**)&T1, g_T1);
    cudaGetSymbolAddress((void**)&T2, g_T2);
    cudaGetSymbolAddress((void**)&M0s, g_M0s);
    cudaGetSymbolAddress((void**)&P0s, g_P0s);
    cudaGetSymbolAddress((void**)&P1s, g_P1s);
    cudaGetSymbolAddress((void**)&T1s, g_T1s);
    cudaGetSymbolAddress((void**)&Wbh, g_Wbh);
    cudaGetSymbolAddress((void**)&Wbl, g_Wbl);

    k_fused<<<DEG_NB + WPREP_NB, 256>>>(dst, W0, W1, W2, W3);        // #0
    k_base<<<(NN + 255) / 256, 256>>>();                             // #1
    k_fillpad<<<FILL_NB + PAD_NB, 256>>>(src, dst, x);               // #2

    const int sgrid = NN / 32;    // 5000
    const int ggrid = NN / 128;   // 1250

    // ---- layer 0 ----  (#3 = first spmm — ncu target)
    k_spmm<1, true><<<sgrid, 256>>>(M0s, T1, T1s);
    k_spmm<1, false><<<sgrid, 256>>>(T1s, T2, nullptr);
    k_gemm_tc<true><<<ggrid, 256>>>(M0, T1, T2, Wbh + 0 * 6144, Wbl + 0 * 6144, b0, P0, P0s);

    // ---- layer 1 ----
    k_spmm<2, true><<<sgrid, 256>>>(P0s, T1, T1s);
    k_spmm<2, false><<<sgrid, 256>>>(T1s, T2, nullptr);
    k_gemm_tc<true><<<ggrid, 256>>>(P0, T1, T2, Wbh + 1 * 6144, Wbl + 1 * 6144, b1, P1, P1s);

    // ---- layer 2 ----
    k_spmm<2, true><<<sgrid, 256>>>(P1s, T1, T1s);
    k_spmm<2, false><<<sgrid, 256>>>(T1s, T2, nullptr);
    k_gemm_tc<true><<<ggrid, 256>>>(P1, T1, T2, Wbh + 2 * 6144, Wbl + 2 * 6144, b2, P0, P0s);

    // ---- layer 3 ----
    k_spmm<2, true><<<sgrid, 256>>>(P0s, T1, T1s);
    k_spmm<2, false><<<sgrid, 256>>>(T1s, T2, nullptr);
    k_gemm_tc<false><<<ggrid, 256>>>(P0, T1, T2, Wbh + 3 * 6144, Wbl + 3 * 6144, b3, P1, nullptr);

    // ---- pooling ----
    k_pool<<<GG, 256>>>(P1, Wg, bg, out);
}